// round 1
// baseline (speedup 1.0000x reference)
#include <cuda_runtime.h>

#define NB 16
#define NC 512
#define NHW 1024
#define NG 32
#define CPG 16   // channels per group

// Scratch (allocation-free rule: __device__ globals)
__device__ float g_xn[(size_t)NB * NC * NHW];
__device__ float g_q [(size_t)NB * NC * NHW];
__device__ float g_k [(size_t)NB * NC * NHW];
__device__ float g_v [(size_t)NB * NC * NHW];
__device__ float g_attn[(size_t)NB * NHW * NHW];
__device__ float g_o [(size_t)NB * NC * NHW];

// ---------------------------------------------------------------------------
// GroupNorm: one block per (batch, group). 16 ch * 1024 spatial = 16384 elems.
// ---------------------------------------------------------------------------
__global__ void __launch_bounds__(256) gn_kernel(const float* __restrict__ x,
                                                 const float* __restrict__ gamma,
                                                 const float* __restrict__ beta) {
    const int bg = blockIdx.x;
    const int b = bg >> 5, g = bg & 31;
    const size_t base = ((size_t)b * NC + (size_t)g * CPG) * NHW;
    const float* xp = x + base;
    float* op = g_xn + base;
    const int N = CPG * NHW;  // 16384

    float s = 0.f, ss = 0.f;
    for (int i = threadIdx.x * 4; i < N; i += blockDim.x * 4) {
        float4 v = *(const float4*)(xp + i);
        s  += v.x + v.y + v.z + v.w;
        ss += v.x*v.x + v.y*v.y + v.z*v.z + v.w*v.w;
    }
    __shared__ float rs[8], rq[8];
    #pragma unroll
    for (int o = 16; o > 0; o >>= 1) {
        s  += __shfl_xor_sync(0xffffffffu, s,  o);
        ss += __shfl_xor_sync(0xffffffffu, ss, o);
    }
    if ((threadIdx.x & 31) == 0) { rs[threadIdx.x >> 5] = s; rq[threadIdx.x >> 5] = ss; }
    __syncthreads();
    s = 0.f; ss = 0.f;
    #pragma unroll
    for (int w = 0; w < 8; w++) { s += rs[w]; ss += rq[w]; }

    const float mean = s / (float)N;
    const float var  = ss / (float)N - mean * mean;
    const float rstd = rsqrtf(var + 1e-6f);

    for (int i = threadIdx.x * 4; i < N; i += blockDim.x * 4) {
        const int c = g * CPG + (i >> 10);  // same channel for all 4 lanes of the float4
        const float gm = gamma[c] * rstd;
        const float bt = beta[c] - mean * gm;
        float4 v = *(const float4*)(xp + i);
        float4 o4;
        o4.x = v.x * gm + bt; o4.y = v.y * gm + bt;
        o4.z = v.z * gm + bt; o4.w = v.w * gm + bt;
        *(float4*)(op + i) = o4;
    }
}

// ---------------------------------------------------------------------------
// NN SGEMM: Out[b][m][n] = sum_k W[m][k] * X[b][k][n] + bias[m] (+ resid)
// M=512, N=1024, K=512. Tile 64x64x16, 256 threads, 4x4 per thread.
// Used for q/k/v convs (resid=nullptr) and the final proj (resid=x -> d_out).
// ---------------------------------------------------------------------------
__global__ void __launch_bounds__(256) gemm_nn_kernel(const float* __restrict__ W,
                                                      const float* __restrict__ X,
                                                      const float* __restrict__ bias,
                                                      const float* __restrict__ resid,
                                                      float* __restrict__ Out) {
    const int Md = 512, Nd = 1024, Kd = 512;
    const int b  = blockIdx.z;
    const int m0 = blockIdx.y * 64, n0 = blockIdx.x * 64;
    const int tid = threadIdx.x;
    const int tx = tid & 15, ty = tid >> 4;

    __shared__ float As[16][64];
    __shared__ float Bs[16][64];

    const float* Xb = X + (size_t)b * Kd * Nd;
    float acc[4][4] = {};

    const int ra = tid >> 2, ka = (tid & 3) << 2;   // A tile: 64 rows(m) x 16 (k)
    const int rb = tid >> 4, nb_ = (tid & 15) << 2; // B tile: 16 rows(k) x 64 (n)

    for (int k0 = 0; k0 < Kd; k0 += 16) {
        float4 a4 = *(const float4*)&W[(size_t)(m0 + ra) * Kd + k0 + ka];
        As[ka + 0][ra] = a4.x; As[ka + 1][ra] = a4.y;
        As[ka + 2][ra] = a4.z; As[ka + 3][ra] = a4.w;
        *(float4*)&Bs[rb][nb_] = *(const float4*)&Xb[(size_t)(k0 + rb) * Nd + n0 + nb_];
        __syncthreads();
        #pragma unroll
        for (int k = 0; k < 16; k++) {
            float4 av = *(const float4*)&As[k][ty << 2];
            float4 bv = *(const float4*)&Bs[k][tx << 2];
            float am[4] = {av.x, av.y, av.z, av.w};
            float bn[4] = {bv.x, bv.y, bv.z, bv.w};
            #pragma unroll
            for (int i = 0; i < 4; i++)
                #pragma unroll
                for (int j = 0; j < 4; j++)
                    acc[i][j] += am[i] * bn[j];
        }
        __syncthreads();
    }

    float* Ob = Out + (size_t)b * Md * Nd;
    const float* Rb = resid ? resid + (size_t)b * Md * Nd : nullptr;
    const int n = n0 + (tx << 2);
    #pragma unroll
    for (int i = 0; i < 4; i++) {
        const int m = m0 + (ty << 2) + i;
        const float bm = bias[m];
        float4 o4;
        o4.x = acc[i][0] + bm; o4.y = acc[i][1] + bm;
        o4.z = acc[i][2] + bm; o4.w = acc[i][3] + bm;
        if (Rb) {
            float4 r4 = *(const float4*)&Rb[(size_t)m * Nd + n];
            o4.x += r4.x; o4.y += r4.y; o4.z += r4.z; o4.w += r4.w;
        }
        *(float4*)&Ob[(size_t)m * Nd + n] = o4;
    }
}

// ---------------------------------------------------------------------------
// Energy (TN): E[b][i][j] = alpha * sum_c q[b][c][i] * k[b][c][j]
// M=N=1024, K=512. Both operands are K-major -> direct coalesced tile loads.
// ---------------------------------------------------------------------------
__global__ void __launch_bounds__(256) energy_kernel() {
    const int b  = blockIdx.z;
    const int m0 = blockIdx.y * 64, n0 = blockIdx.x * 64;
    const int tid = threadIdx.x;
    const int tx = tid & 15, ty = tid >> 4;

    __shared__ float As[16][64];
    __shared__ float Bs[16][64];

    const float* Q  = g_q + (size_t)b * NC * NHW;
    const float* Kp = g_k + (size_t)b * NC * NHW;

    const int r = tid >> 4, cc = (tid & 15) << 2;
    float acc[4][4] = {};

    for (int k0 = 0; k0 < NC; k0 += 16) {
        *(float4*)&As[r][cc] = *(const float4*)&Q [(size_t)(k0 + r) * NHW + m0 + cc];
        *(float4*)&Bs[r][cc] = *(const float4*)&Kp[(size_t)(k0 + r) * NHW + n0 + cc];
        __syncthreads();
        #pragma unroll
        for (int k = 0; k < 16; k++) {
            float4 av = *(const float4*)&As[k][ty << 2];
            float4 bv = *(const float4*)&Bs[k][tx << 2];
            float am[4] = {av.x, av.y, av.z, av.w};
            float bn[4] = {bv.x, bv.y, bv.z, bv.w};
            #pragma unroll
            for (int i = 0; i < 4; i++)
                #pragma unroll
                for (int j = 0; j < 4; j++)
                    acc[i][j] += am[i] * bn[j];
        }
        __syncthreads();
    }

    const float alpha = 0.04419417382415922f;  // 512^-0.5
    float* E = g_attn + (size_t)b * NHW * NHW;
    const int n = n0 + (tx << 2);
    #pragma unroll
    for (int i = 0; i < 4; i++) {
        const int m = m0 + (ty << 2) + i;
        float4 o4;
        o4.x = acc[i][0] * alpha; o4.y = acc[i][1] * alpha;
        o4.z = acc[i][2] * alpha; o4.w = acc[i][3] * alpha;
        *(float4*)&E[(size_t)m * NHW + n] = o4;
    }
}

// ---------------------------------------------------------------------------
// Softmax over last dim (1024), in place on g_attn. One block per row.
// ---------------------------------------------------------------------------
__global__ void __launch_bounds__(256) softmax_kernel() {
    const size_t row = blockIdx.x;
    float* p = g_attn + row * NHW;
    const int tid = threadIdx.x;

    float4 v = ((float4*)p)[tid];
    float mx = fmaxf(fmaxf(v.x, v.y), fmaxf(v.z, v.w));
    __shared__ float sm[8], ssum[8];
    #pragma unroll
    for (int o = 16; o > 0; o >>= 1) mx = fmaxf(mx, __shfl_xor_sync(0xffffffffu, mx, o));
    if ((tid & 31) == 0) sm[tid >> 5] = mx;
    __syncthreads();
    mx = sm[0];
    #pragma unroll
    for (int w = 1; w < 8; w++) mx = fmaxf(mx, sm[w]);

    v.x = __expf(v.x - mx); v.y = __expf(v.y - mx);
    v.z = __expf(v.z - mx); v.w = __expf(v.w - mx);
    float s = v.x + v.y + v.z + v.w;
    #pragma unroll
    for (int o = 16; o > 0; o >>= 1) s += __shfl_xor_sync(0xffffffffu, s, o);
    if ((tid & 31) == 0) ssum[tid >> 5] = s;
    __syncthreads();
    s = 0.f;
    #pragma unroll
    for (int w = 0; w < 8; w++) s += ssum[w];

    const float inv = 1.0f / s;
    v.x *= inv; v.y *= inv; v.z *= inv; v.w *= inv;
    ((float4*)p)[tid] = v;
}

// ---------------------------------------------------------------------------
// AttnV (NT): O[b][c][i] = sum_j V[b][c][j] * attn[b][i][j]
// M=512 (c), N=1024 (i), K=1024 (j). Both operands j-contiguous.
// ---------------------------------------------------------------------------
__global__ void __launch_bounds__(256) attnv_kernel() {
    const int b  = blockIdx.z;
    const int m0 = blockIdx.y * 64, n0 = blockIdx.x * 64;
    const int tid = threadIdx.x;
    const int tx = tid & 15, ty = tid >> 4;

    __shared__ float As[16][64];
    __shared__ float Bs[16][64];

    const float* V  = g_v    + (size_t)b * NC * NHW;
    const float* Ap = g_attn + (size_t)b * NHW * NHW;

    const int r = tid >> 2, kc = (tid & 3) << 2;
    float acc[4][4] = {};

    for (int k0 = 0; k0 < NHW; k0 += 16) {
        float4 a4 = *(const float4*)&V [(size_t)(m0 + r) * NHW + k0 + kc];
        As[kc + 0][r] = a4.x; As[kc + 1][r] = a4.y;
        As[kc + 2][r] = a4.z; As[kc + 3][r] = a4.w;
        float4 b4 = *(const float4*)&Ap[(size_t)(n0 + r) * NHW + k0 + kc];
        Bs[kc + 0][r] = b4.x; Bs[kc + 1][r] = b4.y;
        Bs[kc + 2][r] = b4.z; Bs[kc + 3][r] = b4.w;
        __syncthreads();
        #pragma unroll
        for (int k = 0; k < 16; k++) {
            float4 av = *(const float4*)&As[k][ty << 2];
            float4 bv = *(const float4*)&Bs[k][tx << 2];
            float am[4] = {av.x, av.y, av.z, av.w};
            float bn[4] = {bv.x, bv.y, bv.z, bv.w};
            #pragma unroll
            for (int i = 0; i < 4; i++)
                #pragma unroll
                for (int j = 0; j < 4; j++)
                    acc[i][j] += am[i] * bn[j];
        }
        __syncthreads();
    }

    float* O = g_o + (size_t)b * NC * NHW;
    const int n = n0 + (tx << 2);
    #pragma unroll
    for (int i = 0; i < 4; i++) {
        const int m = m0 + (ty << 2) + i;
        float4 o4 = {acc[i][0], acc[i][1], acc[i][2], acc[i][3]};
        *(float4*)&O[(size_t)m * NHW + n] = o4;
    }
}

// ---------------------------------------------------------------------------
// Launch
// ---------------------------------------------------------------------------
extern "C" void kernel_launch(void* const* d_in, const int* in_sizes, int n_in,
                              void* d_out, int out_size) {
    const float* x     = (const float*)d_in[0];
    const float* gamma = (const float*)d_in[1];
    const float* beta  = (const float*)d_in[2];
    const float* wq = (const float*)d_in[3]; const float* bq = (const float*)d_in[4];
    const float* wk = (const float*)d_in[5]; const float* bk = (const float*)d_in[6];
    const float* wv = (const float*)d_in[7]; const float* bv = (const float*)d_in[8];
    const float* wp = (const float*)d_in[9]; const float* bp = (const float*)d_in[10];
    float* out = (float*)d_out;

    float *p_xn, *p_q, *p_k, *p_v, *p_o;
    cudaGetSymbolAddress((void**)&p_xn, g_xn);
    cudaGetSymbolAddress((void**)&p_q,  g_q);
    cudaGetSymbolAddress((void**)&p_k,  g_k);
    cudaGetSymbolAddress((void**)&p_v,  g_v);
    cudaGetSymbolAddress((void**)&p_o,  g_o);

    // 1. GroupNorm
    gn_kernel<<<NB * NG, 256>>>(x, gamma, beta);

    // 2. q, k, v 1x1 convs
    dim3 gc(NHW / 64, NC / 64, NB);
    gemm_nn_kernel<<<gc, 256>>>(wq, p_xn, bq, nullptr, p_q);
    gemm_nn_kernel<<<gc, 256>>>(wk, p_xn, bk, nullptr, p_k);
    gemm_nn_kernel<<<gc, 256>>>(wv, p_xn, bv, nullptr, p_v);

    // 3. energy = scale * q^T k
    dim3 ge(NHW / 64, NHW / 64, NB);
    energy_kernel<<<ge, 256>>>();

    // 4. softmax rows
    softmax_kernel<<<NB * NHW, 256>>>();

    // 5. attn . V
    attnv_kernel<<<gc, 256>>>();

    // 6. proj + bias + residual -> d_out
    gemm_nn_kernel<<<gc, 256>>>(wp, p_o, bp, x, out);
}

// round 4
// speedup vs baseline: 4.6942x; 4.6942x over previous
#include <cuda_runtime.h>
#include <cstdint>

#define NB 16
#define NC 512
#define NHW 1024
#define NG 32
#define CPG 16

// Scratch (allocation-free rule: __device__ globals)
__device__ float g_xn[(size_t)NB * NC * NHW];
__device__ float g_q [(size_t)NB * NC * NHW];
__device__ float g_k [(size_t)NB * NC * NHW];
__device__ float g_v [(size_t)NB * NC * NHW];
__device__ float g_attn[(size_t)NB * NHW * NHW];
__device__ float g_o [(size_t)NB * NC * NHW];

// ---------------------------------------------------------------------------
// helpers
// ---------------------------------------------------------------------------
__device__ __forceinline__ uint32_t tf32cvt(float f) {
    uint32_t u;
    asm("cvt.rna.tf32.f32 %0, %1;" : "=r"(u) : "f"(f));
    return u;
}

__device__ __forceinline__ void mma_tf32(float* c, const uint32_t* a, const uint32_t* b) {
    asm volatile(
        "mma.sync.aligned.m16n8k8.row.col.f32.tf32.tf32.f32 "
        "{%0,%1,%2,%3}, {%4,%5,%6,%7}, {%8,%9}, {%0,%1,%2,%3};"
        : "+f"(c[0]), "+f"(c[1]), "+f"(c[2]), "+f"(c[3])
        : "r"(a[0]), "r"(a[1]), "r"(a[2]), "r"(a[3]), "r"(b[0]), "r"(b[1]));
}

__device__ __forceinline__ void cpasync16(uint32_t smem, const float* g) {
    asm volatile("cp.async.cg.shared.global [%0], [%1], 16;\n" :: "r"(smem), "l"(g));
}
__device__ __forceinline__ void cp_commit() { asm volatile("cp.async.commit_group;\n"); }
__device__ __forceinline__ void cp_wait0()  { asm volatile("cp.async.wait_group 0;\n"); }

// ---------------------------------------------------------------------------
// tf32 GEMM:  C[b](m,n) = alpha * sum_k A(m,k)*B(k,n) [+ bias(m)] [+ R(m,n)]
//   TA: A(m,k) = A[k*lda + m]   else A[m*lda + k]
//   TB: B(k,n) = B[n*ldb + k]   else B[k*ldb + n]
// Block 128x128x16, 256 threads, warps 2(m) x 4(n), warp tile 64x32.
// cp.async double buffered. Smem padded for conflict-free fill + frag loads.
// ---------------------------------------------------------------------------
template<bool TA, bool TB, bool HAS_BIAS, bool HAS_RES>
__global__ void __launch_bounds__(256, 2) mm_tf32(
    const float* __restrict__ A, const float* __restrict__ B,
    const float* __restrict__ bias, const float* __restrict__ R,
    float* __restrict__ C,
    int M, int N, int K, int lda, int ldb,
    size_t sA, size_t sB, size_t sC, float alpha)
{
    constexpr int BM = 128, BN = 128, BK = 16;
    constexpr int ASZ = TA ? BK * 132 : BM * 20;  // floats
    constexpr int BSZ = TB ? BN * 20  : BK * 132;

    __shared__ float As[2][ASZ];
    __shared__ float Bs[2][BSZ];

    const int tid  = threadIdx.x;
    const int lane = tid & 31, warp = tid >> 5;
    const int wm = (warp >> 2) * 64;   // 2 warps along m
    const int wn = (warp & 3) * 32;    // 4 warps along n
    const int g  = lane >> 2, tq = lane & 3;

    const int bz = blockIdx.z;
    const int m0 = blockIdx.y * BM, n0 = blockIdx.x * BN;

    const float* Ab = A + (size_t)bz * sA;
    const float* Bb = B + (size_t)bz * sB;
    float*       Cb = C + (size_t)bz * sC;
    const float* Rb = HAS_RES ? R + (size_t)bz * sC : nullptr;

    // smem index: (k, m/n) -> word offset
    #define IDXA(k, m) (TA ? (k) * 132 + (m) : (m) * 20 + (k))
    #define IDXB(k, n) (TB ? (n) * 20 + (k) : (k) * 132 + (n))

    const uint32_t sa0 = (uint32_t)__cvta_generic_to_shared(&As[0][0]);
    const uint32_t sa1 = (uint32_t)__cvta_generic_to_shared(&As[1][0]);
    const uint32_t sb0 = (uint32_t)__cvta_generic_to_shared(&Bs[0][0]);
    const uint32_t sb1 = (uint32_t)__cvta_generic_to_shared(&Bs[1][0]);

    auto issue = [&](int kb, int s) {
        const uint32_t sa = s ? sa1 : sa0;
        const uint32_t sb = s ? sb1 : sb0;
        #pragma unroll
        for (int i = 0; i < 2; i++) {
            const int idx = i * 256 + tid;  // 0..511 float4 slots
            if (!TA) {
                const int row = idx >> 2, kf = (idx & 3) << 2;
                cpasync16(sa + (uint32_t)(row * 20 + kf) * 4,
                          Ab + (size_t)(m0 + row) * lda + kb + kf);
            } else {
                const int kr = idx >> 5, mf = (idx & 31) << 2;
                cpasync16(sa + (uint32_t)(kr * 132 + mf) * 4,
                          Ab + (size_t)(kb + kr) * lda + m0 + mf);
            }
            if (!TB) {
                const int kr = idx >> 5, nf = (idx & 31) << 2;
                cpasync16(sb + (uint32_t)(kr * 132 + nf) * 4,
                          Bb + (size_t)(kb + kr) * ldb + n0 + nf);
            } else {
                const int row = idx >> 2, kf = (idx & 3) << 2;
                cpasync16(sb + (uint32_t)(row * 20 + kf) * 4,
                          Bb + (size_t)(n0 + row) * ldb + kb + kf);
            }
        }
        cp_commit();
    };

    float acc[4][4][4] = {};

    const int nk = K / BK;
    issue(0, 0);

    for (int t = 0; t < nk; t++) {
        cp_wait0();
        __syncthreads();
        if (t + 1 < nk) issue((t + 1) * BK, (t + 1) & 1);

        const float* As_ = As[t & 1];
        const float* Bs_ = Bs[t & 1];

        #pragma unroll
        for (int kk = 0; kk < BK; kk += 8) {
            uint32_t af[4][4];
            #pragma unroll
            for (int mi = 0; mi < 4; mi++) {
                const int mb = wm + mi * 16;
                af[mi][0] = tf32cvt(As_[IDXA(kk + tq,     mb + g)]);
                af[mi][1] = tf32cvt(As_[IDXA(kk + tq,     mb + g + 8)]);
                af[mi][2] = tf32cvt(As_[IDXA(kk + tq + 4, mb + g)]);
                af[mi][3] = tf32cvt(As_[IDXA(kk + tq + 4, mb + g + 8)]);
            }
            uint32_t bf[4][2];
            #pragma unroll
            for (int ni = 0; ni < 4; ni++) {
                const int nb_ = wn + ni * 8;
                bf[ni][0] = tf32cvt(Bs_[IDXB(kk + tq,     nb_ + g)]);
                bf[ni][1] = tf32cvt(Bs_[IDXB(kk + tq + 4, nb_ + g)]);
            }
            #pragma unroll
            for (int mi = 0; mi < 4; mi++)
                #pragma unroll
                for (int ni = 0; ni < 4; ni++)
                    mma_tf32(acc[mi][ni], af[mi], bf[ni]);
        }
    }
    #undef IDXA
    #undef IDXB

    // Epilogue
    #pragma unroll
    for (int mi = 0; mi < 4; mi++) {
        const int r0 = m0 + wm + mi * 16 + g;
        const int r1 = r0 + 8;
        const float bv0 = HAS_BIAS ? bias[r0] : 0.f;
        const float bv1 = HAS_BIAS ? bias[r1] : 0.f;
        #pragma unroll
        for (int ni = 0; ni < 4; ni++) {
            const int col = n0 + wn + ni * 8 + tq * 2;
            float2 v0, v1;
            v0.x = acc[mi][ni][0] * alpha + bv0;
            v0.y = acc[mi][ni][1] * alpha + bv0;
            v1.x = acc[mi][ni][2] * alpha + bv1;
            v1.y = acc[mi][ni][3] * alpha + bv1;
            if (HAS_RES) {
                float2 r0v = *(const float2*)&Rb[(size_t)r0 * N + col];
                float2 r1v = *(const float2*)&Rb[(size_t)r1 * N + col];
                v0.x += r0v.x; v0.y += r0v.y;
                v1.x += r1v.x; v1.y += r1v.y;
            }
            *(float2*)&Cb[(size_t)r0 * N + col] = v0;
            *(float2*)&Cb[(size_t)r1 * N + col] = v1;
        }
    }
}

// ---------------------------------------------------------------------------
// GroupNorm: one block per (batch, group).
// ---------------------------------------------------------------------------
__global__ void __launch_bounds__(256) gn_kernel(const float* __restrict__ x,
                                                 const float* __restrict__ gamma,
                                                 const float* __restrict__ beta) {
    const int bg = blockIdx.x;
    const int b = bg >> 5, g = bg & 31;
    const size_t base = ((size_t)b * NC + (size_t)g * CPG) * NHW;
    const float* xp = x + base;
    float* op = g_xn + base;
    const int N = CPG * NHW;

    float s = 0.f, ss = 0.f;
    for (int i = threadIdx.x * 4; i < N; i += blockDim.x * 4) {
        float4 v = *(const float4*)(xp + i);
        s  += v.x + v.y + v.z + v.w;
        ss += v.x*v.x + v.y*v.y + v.z*v.z + v.w*v.w;
    }
    __shared__ float rs[8], rq[8];
    #pragma unroll
    for (int o = 16; o > 0; o >>= 1) {
        s  += __shfl_xor_sync(0xffffffffu, s,  o);
        ss += __shfl_xor_sync(0xffffffffu, ss, o);
    }
    if ((threadIdx.x & 31) == 0) { rs[threadIdx.x >> 5] = s; rq[threadIdx.x >> 5] = ss; }
    __syncthreads();
    s = 0.f; ss = 0.f;
    #pragma unroll
    for (int w = 0; w < 8; w++) { s += rs[w]; ss += rq[w]; }

    const float mean = s / (float)N;
    const float var  = ss / (float)N - mean * mean;
    const float rstd = rsqrtf(var + 1e-6f);

    for (int i = threadIdx.x * 4; i < N; i += blockDim.x * 4) {
        const int c = g * CPG + (i >> 10);
        const float gm = gamma[c] * rstd;
        const float bt = beta[c] - mean * gm;
        float4 v = *(const float4*)(xp + i);
        float4 o4;
        o4.x = v.x * gm + bt; o4.y = v.y * gm + bt;
        o4.z = v.z * gm + bt; o4.w = v.w * gm + bt;
        *(float4*)(op + i) = o4;
    }
}

// ---------------------------------------------------------------------------
// Softmax over last dim (1024), in place. One block (256 thr) per row.
// ---------------------------------------------------------------------------
__global__ void __launch_bounds__(256) softmax_kernel() {
    const size_t row = blockIdx.x;
    float* p = g_attn + row * NHW;
    const int tid = threadIdx.x;

    float4 v = ((float4*)p)[tid];
    float mx = fmaxf(fmaxf(v.x, v.y), fmaxf(v.z, v.w));
    __shared__ float sm[8], ssum[8];
    #pragma unroll
    for (int o = 16; o > 0; o >>= 1) mx = fmaxf(mx, __shfl_xor_sync(0xffffffffu, mx, o));
    if ((tid & 31) == 0) sm[tid >> 5] = mx;
    __syncthreads();
    mx = sm[0];
    #pragma unroll
    for (int w = 1; w < 8; w++) mx = fmaxf(mx, sm[w]);

    v.x = __expf(v.x - mx); v.y = __expf(v.y - mx);
    v.z = __expf(v.z - mx); v.w = __expf(v.w - mx);
    float s = v.x + v.y + v.z + v.w;
    #pragma unroll
    for (int o = 16; o > 0; o >>= 1) s += __shfl_xor_sync(0xffffffffu, s, o);
    if ((tid & 31) == 0) ssum[tid >> 5] = s;
    __syncthreads();
    s = 0.f;
    #pragma unroll
    for (int w = 0; w < 8; w++) s += ssum[w];

    const float inv = 1.0f / s;
    v.x *= inv; v.y *= inv; v.z *= inv; v.w *= inv;
    ((float4*)p)[tid] = v;
}

// ---------------------------------------------------------------------------
// Launch
// ---------------------------------------------------------------------------
extern "C" void kernel_launch(void* const* d_in, const int* in_sizes, int n_in,
                              void* d_out, int out_size) {
    const float* x     = (const float*)d_in[0];
    const float* gamma = (const float*)d_in[1];
    const float* beta  = (const float*)d_in[2];
    const float* wq = (const float*)d_in[3]; const float* bq = (const float*)d_in[4];
    const float* wk = (const float*)d_in[5]; const float* bk = (const float*)d_in[6];
    const float* wv = (const float*)d_in[7]; const float* bv = (const float*)d_in[8];
    const float* wp = (const float*)d_in[9]; const float* bp = (const float*)d_in[10];
    float* out = (float*)d_out;

    float *p_xn, *p_q, *p_k, *p_v, *p_attn, *p_o;
    cudaGetSymbolAddress((void**)&p_xn,   g_xn);
    cudaGetSymbolAddress((void**)&p_q,    g_q);
    cudaGetSymbolAddress((void**)&p_k,    g_k);
    cudaGetSymbolAddress((void**)&p_v,    g_v);
    cudaGetSymbolAddress((void**)&p_attn, g_attn);
    cudaGetSymbolAddress((void**)&p_o,    g_o);

    const size_t sX = (size_t)NC * NHW;     // per-batch C x HW
    const size_t sE = (size_t)NHW * NHW;    // per-batch HW x HW

    // 1. GroupNorm
    gn_kernel<<<NB * NG, 256>>>(x, gamma, beta);

    // 2. q, k, v 1x1 convs:  C(512x1024) = W(512x512) * Xn(512x1024) + b
    dim3 gc(NHW / 128, NC / 128, NB);
    mm_tf32<false,false,true,false><<<gc, 256>>>(wq, p_xn, bq, nullptr, p_q,
        NC, NHW, NC, NC, NHW, 0, sX, sX, 1.f);
    mm_tf32<false,false,true,false><<<gc, 256>>>(wk, p_xn, bk, nullptr, p_k,
        NC, NHW, NC, NC, NHW, 0, sX, sX, 1.f);
    mm_tf32<false,false,true,false><<<gc, 256>>>(wv, p_xn, bv, nullptr, p_v,
        NC, NHW, NC, NC, NHW, 0, sX, sX, 1.f);

    // 3. energy(1024x1024) = alpha * q^T k   (A = q, TA; B = k)
    dim3 ge(NHW / 128, NHW / 128, NB);
    mm_tf32<true,false,false,false><<<ge, 256>>>(p_q, p_k, nullptr, nullptr, p_attn,
        NHW, NHW, NC, NHW, NHW, sX, sX, sE, 0.04419417382415922f);

    // 4. softmax rows
    softmax_kernel<<<NB * NHW, 256>>>();

    // 5. O(512x1024) = V(512x1024) * attn^T   (B = attn, TB)
    mm_tf32<false,true,false,false><<<gc, 256>>>(p_v, p_attn, nullptr, nullptr, p_o,
        NC, NHW, NHW, NHW, NHW, sX, sE, sX, 1.f);

    // 6. proj + bias + residual -> d_out
    mm_tf32<false,false,true,true><<<gc, 256>>>(wp, p_o, bp, x, out,
        NC, NHW, NC, NC, NHW, 0, sX, sX, 1.f);
}

// round 5
// speedup vs baseline: 11.4314x; 2.4352x over previous
#include <cuda_runtime.h>
#include <cuda_bf16.h>
#include <cstdint>

#define NB 16
#define NC 512
#define NHW 1024
#define NG 32
#define CPG 16

typedef __nv_bfloat16 bf16;

// Scratch (allocation-free rule: __device__ globals)
__device__ bf16  g_xn[(size_t)NB * NC * NHW];
__device__ bf16  g_q [(size_t)NB * NC * NHW];
__device__ bf16  g_k [(size_t)NB * NC * NHW];
__device__ bf16  g_v [(size_t)NB * NC * NHW];
__device__ bf16  g_o [(size_t)NB * NC * NHW];
__device__ float g_e [(size_t)NB * NHW * NHW];     // energy, f32 through softmax
__device__ bf16  g_ah[(size_t)NB * NHW * NHW];     // attn, bf16 for GEMM
__device__ bf16  g_wq[NC * NC], g_wk[NC * NC], g_wv[NC * NC], g_wp[NC * NC];

// ---------------------------------------------------------------------------
// PTX helpers
// ---------------------------------------------------------------------------
__device__ __forceinline__ void cpasync16(uint32_t smem, const bf16* g) {
    asm volatile("cp.async.cg.shared.global [%0], [%1], 16;\n" :: "r"(smem), "l"(g));
}
__device__ __forceinline__ void cp_commit() { asm volatile("cp.async.commit_group;\n"); }
template<int N> __device__ __forceinline__ void cp_wait() {
    asm volatile("cp.async.wait_group %0;\n" :: "n"(N));
}
__device__ __forceinline__ void ldsm4(uint32_t& r0, uint32_t& r1, uint32_t& r2, uint32_t& r3,
                                      uint32_t a) {
    asm volatile("ldmatrix.sync.aligned.m8n8.x4.shared.b16 {%0,%1,%2,%3}, [%4];"
                 : "=r"(r0), "=r"(r1), "=r"(r2), "=r"(r3) : "r"(a));
}
__device__ __forceinline__ void ldsm4t(uint32_t& r0, uint32_t& r1, uint32_t& r2, uint32_t& r3,
                                       uint32_t a) {
    asm volatile("ldmatrix.sync.aligned.m8n8.x4.trans.shared.b16 {%0,%1,%2,%3}, [%4];"
                 : "=r"(r0), "=r"(r1), "=r"(r2), "=r"(r3) : "r"(a));
}
__device__ __forceinline__ void mma_bf16(float* c, const uint32_t* a, const uint32_t* b) {
    asm volatile(
        "mma.sync.aligned.m16n8k16.row.col.f32.bf16.bf16.f32 "
        "{%0,%1,%2,%3}, {%4,%5,%6,%7}, {%8,%9}, {%0,%1,%2,%3};"
        : "+f"(c[0]), "+f"(c[1]), "+f"(c[2]), "+f"(c[3])
        : "r"(a[0]), "r"(a[1]), "r"(a[2]), "r"(a[3]), "r"(b[0]), "r"(b[1]));
}

// ---------------------------------------------------------------------------
// bf16 GEMM:  C[b](m,n) = alpha * sum_k A(m,k)*B(k,n) [+ bias] [+ R]
//   AKM:  A global stored (k,m), m contiguous (else (m,k), k contiguous)
//   BKN:  B global stored (k,n), n contiguous (else (n,k), k contiguous)
// Block 128x128x32, 256 thr, warps 2(m)x4(n), 3-stage cp.async, LDSM frags.
// Smem tiles: (m,k)/(n,k): 128 rows x 32h, chunk c^( (row>>1)&3 )
//             (k,m)/(k,n): 32 rows x 128h, chunk c^( krow&7 )
// OUTF: 0 = bf16 out, 1 = f32 out
// ---------------------------------------------------------------------------
template<bool AKM, bool BKN, bool OUTF, bool BIAS, bool RES>
__global__ void __launch_bounds__(256, 2) mm_bf16(
    const bf16* __restrict__ A, const bf16* __restrict__ B,
    const float* __restrict__ bias, const float* __restrict__ R,
    void* __restrict__ C,
    int N, int K, int lda, int ldb,
    size_t sA, size_t sB, size_t sC, float alpha)
{
    constexpr int BK = 32;
    __shared__ __align__(16) bf16 As[3][4096];
    __shared__ __align__(16) bf16 Bs[3][4096];

    const int tid  = threadIdx.x;
    const int lane = tid & 31;
    const int warp = tid >> 5;
    const int wm = (warp >> 2) * 64;
    const int wn = (warp & 3) * 32;
    const int g  = lane >> 2, tq = lane & 3;

    const int bz = blockIdx.z;
    const int m0 = blockIdx.y * 128, n0 = blockIdx.x * 128;

    const bf16* Ab = A + (size_t)bz * sA;
    const bf16* Bb = B + (size_t)bz * sB;

    const uint32_t sa_base = (uint32_t)__cvta_generic_to_shared(&As[0][0]);
    const uint32_t sb_base = (uint32_t)__cvta_generic_to_shared(&Bs[0][0]);

    // --- precompute per-lane LDSM offsets (bytes within one stage buffer) ---
    const int mat = lane >> 3, rin = lane & 7;
    uint32_t offA[4][2], offB[2][2];
    #pragma unroll
    for (int mi = 0; mi < 4; mi++)
        #pragma unroll
        for (int kk = 0; kk < 2; kk++) {
            if (!AKM) {
                const int row = wm + mi * 16 + ((mat & 1) << 3) + rin;
                const int c   = kk * 2 + (mat >> 1);
                offA[mi][kk] = row * 64 + ((c ^ ((row >> 1) & 3)) << 4);
            } else {
                const int kr = kk * 16 + ((mat >> 1) << 3) + rin;
                const int cm = (wm + mi * 16 + ((mat & 1) << 3)) >> 3;
                offA[mi][kk] = kr * 256 + ((cm ^ (kr & 7)) << 4);
            }
        }
    #pragma unroll
    for (int ni = 0; ni < 2; ni++)
        #pragma unroll
        for (int kk = 0; kk < 2; kk++) {
            if (!BKN) {
                const int row = wn + ni * 16 + ((mat >> 1) << 3) + rin;
                const int c   = kk * 2 + (mat & 1);
                offB[ni][kk] = row * 64 + ((c ^ ((row >> 1) & 3)) << 4);
            } else {
                const int kr = kk * 16 + ((mat & 1) << 3) + rin;
                const int cn = (wn + ni * 16 + ((mat >> 1) << 3)) >> 3;
                offB[ni][kk] = kr * 256 + ((cn ^ (kr & 7)) << 4);
            }
        }

    const int nk = K / BK;

    auto issue = [&](int t) {
        const int kb = t * BK;
        const uint32_t sa = sa_base + (t % 3) * 8192;
        const uint32_t sb = sb_base + (t % 3) * 8192;
        #pragma unroll
        for (int i = 0; i < 2; i++) {
            const int idx = i * 256 + tid;
            if (!AKM) {
                const int row = idx >> 2, c = idx & 3;
                cpasync16(sa + row * 64 + ((c ^ ((row >> 1) & 3)) << 4),
                          Ab + (size_t)(m0 + row) * lda + kb + c * 8);
            } else {
                const int kr = idx >> 4, cm = idx & 15;
                cpasync16(sa + kr * 256 + ((cm ^ (kr & 7)) << 4),
                          Ab + (size_t)(kb + kr) * lda + m0 + cm * 8);
            }
            if (!BKN) {
                const int row = idx >> 2, c = idx & 3;
                cpasync16(sb + row * 64 + ((c ^ ((row >> 1) & 3)) << 4),
                          Bb + (size_t)(n0 + row) * ldb + kb + c * 8);
            } else {
                const int kr = idx >> 4, cn = idx & 15;
                cpasync16(sb + kr * 256 + ((cn ^ (kr & 7)) << 4),
                          Bb + (size_t)(kb + kr) * ldb + n0 + cn * 8);
            }
        }
        cp_commit();
    };

    float acc[4][4][4] = {};

    issue(0);
    issue(1);

    for (int t = 0; t < nk; t++) {
        cp_wait<1>();
        __syncthreads();
        if (t + 2 < nk) issue(t + 2); else cp_commit();

        const uint32_t sa = sa_base + (t % 3) * 8192;
        const uint32_t sb = sb_base + (t % 3) * 8192;

        #pragma unroll
        for (int kk = 0; kk < 2; kk++) {
            uint32_t af[4][4];
            #pragma unroll
            for (int mi = 0; mi < 4; mi++) {
                if (!AKM) ldsm4 (af[mi][0], af[mi][1], af[mi][2], af[mi][3], sa + offA[mi][kk]);
                else      ldsm4t(af[mi][0], af[mi][1], af[mi][2], af[mi][3], sa + offA[mi][kk]);
            }
            uint32_t bfr[4][2];
            #pragma unroll
            for (int ni = 0; ni < 2; ni++) {
                uint32_t b0, b1, b2, b3;
                if (!BKN) ldsm4 (b0, b1, b2, b3, sb + offB[ni][kk]);
                else      ldsm4t(b0, b1, b2, b3, sb + offB[ni][kk]);
                bfr[ni * 2][0] = b0; bfr[ni * 2][1] = b1;
                bfr[ni * 2 + 1][0] = b2; bfr[ni * 2 + 1][1] = b3;
            }
            #pragma unroll
            for (int mi = 0; mi < 4; mi++)
                #pragma unroll
                for (int ni = 0; ni < 4; ni++)
                    mma_bf16(acc[mi][ni], af[mi], bfr[ni]);
        }
        __syncthreads();
    }

    // ---------------- epilogue ----------------
    const float* Rb = RES ? R + (size_t)bz * sC : nullptr;
    #pragma unroll
    for (int mi = 0; mi < 4; mi++) {
        const int r0 = m0 + wm + mi * 16 + g;
        const int r1 = r0 + 8;
        const float bv0 = BIAS ? bias[r0] : 0.f;
        const float bv1 = BIAS ? bias[r1] : 0.f;
        #pragma unroll
        for (int ni = 0; ni < 4; ni++) {
            const int col = n0 + wn + ni * 8 + tq * 2;
            float v00 = acc[mi][ni][0] * alpha + bv0;
            float v01 = acc[mi][ni][1] * alpha + bv0;
            float v10 = acc[mi][ni][2] * alpha + bv1;
            float v11 = acc[mi][ni][3] * alpha + bv1;
            if (RES) {
                float2 x0 = *(const float2*)&Rb[(size_t)r0 * N + col];
                float2 x1 = *(const float2*)&Rb[(size_t)r1 * N + col];
                v00 += x0.x; v01 += x0.y; v10 += x1.x; v11 += x1.y;
            }
            if (OUTF) {
                float* Cb = (float*)C + (size_t)bz * sC;
                *(float2*)&Cb[(size_t)r0 * N + col] = make_float2(v00, v01);
                *(float2*)&Cb[(size_t)r1 * N + col] = make_float2(v10, v11);
            } else {
                bf16* Cb = (bf16*)C + (size_t)bz * sC;
                *(__nv_bfloat162*)&Cb[(size_t)r0 * N + col] =
                    __floats2bfloat162_rn(v00, v01);
                *(__nv_bfloat162*)&Cb[(size_t)r1 * N + col] =
                    __floats2bfloat162_rn(v10, v11);
            }
        }
    }
}

// ---------------------------------------------------------------------------
// Weight f32 -> bf16 (4 matrices of 512x512)
// ---------------------------------------------------------------------------
__global__ void __launch_bounds__(256) wcvt_kernel(const float* __restrict__ wq,
                                                   const float* __restrict__ wk,
                                                   const float* __restrict__ wv,
                                                   const float* __restrict__ wp) {
    const int i = (blockIdx.x * 256 + threadIdx.x) * 4;
    if (i >= NC * NC) return;
    const float* src[4] = {wq, wk, wv, wp};
    bf16* dst[4] = {g_wq, g_wk, g_wv, g_wp};
    #pragma unroll
    for (int j = 0; j < 4; j++) {
        float4 v = *(const float4*)(src[j] + i);
        __nv_bfloat162 p0 = __floats2bfloat162_rn(v.x, v.y);
        __nv_bfloat162 p1 = __floats2bfloat162_rn(v.z, v.w);
        *(__nv_bfloat162*)(dst[j] + i)     = p0;
        *(__nv_bfloat162*)(dst[j] + i + 2) = p1;
    }
}

// ---------------------------------------------------------------------------
// GroupNorm: one block per (batch, group). Writes bf16 xn.
// ---------------------------------------------------------------------------
__global__ void __launch_bounds__(256) gn_kernel(const float* __restrict__ x,
                                                 const float* __restrict__ gamma,
                                                 const float* __restrict__ beta) {
    const int bg = blockIdx.x;
    const int b = bg >> 5, g = bg & 31;
    const size_t base = ((size_t)b * NC + (size_t)g * CPG) * NHW;
    const float* xp = x + base;
    bf16* op = g_xn + base;
    const int N = CPG * NHW;

    float s = 0.f, ss = 0.f;
    for (int i = threadIdx.x * 4; i < N; i += blockDim.x * 4) {
        float4 v = *(const float4*)(xp + i);
        s  += v.x + v.y + v.z + v.w;
        ss += v.x*v.x + v.y*v.y + v.z*v.z + v.w*v.w;
    }
    __shared__ float rs[8], rq[8];
    #pragma unroll
    for (int o = 16; o > 0; o >>= 1) {
        s  += __shfl_xor_sync(0xffffffffu, s,  o);
        ss += __shfl_xor_sync(0xffffffffu, ss, o);
    }
    if ((threadIdx.x & 31) == 0) { rs[threadIdx.x >> 5] = s; rq[threadIdx.x >> 5] = ss; }
    __syncthreads();
    s = 0.f; ss = 0.f;
    #pragma unroll
    for (int w = 0; w < 8; w++) { s += rs[w]; ss += rq[w]; }

    const float mean = s / (float)N;
    const float var  = ss / (float)N - mean * mean;
    const float rstd = rsqrtf(var + 1e-6f);

    for (int i = threadIdx.x * 4; i < N; i += blockDim.x * 4) {
        const int c = g * CPG + (i >> 10);
        const float gm = gamma[c] * rstd;
        const float bt = beta[c] - mean * gm;
        float4 v = *(const float4*)(xp + i);
        __nv_bfloat162 p0 = __floats2bfloat162_rn(v.x * gm + bt, v.y * gm + bt);
        __nv_bfloat162 p1 = __floats2bfloat162_rn(v.z * gm + bt, v.w * gm + bt);
        *(__nv_bfloat162*)(op + i)     = p0;
        *(__nv_bfloat162*)(op + i + 2) = p1;
    }
}

// ---------------------------------------------------------------------------
// Softmax rows of g_e (f32, 1024 wide) -> g_ah (bf16). One block per row.
// ---------------------------------------------------------------------------
__global__ void __launch_bounds__(256) softmax_kernel() {
    const size_t row = blockIdx.x;
    const float* p = g_e + row * NHW;
    bf16* q = g_ah + row * NHW;
    const int tid = threadIdx.x;

    float4 v = ((const float4*)p)[tid];
    float mx = fmaxf(fmaxf(v.x, v.y), fmaxf(v.z, v.w));
    __shared__ float sm[8], ssum[8];
    #pragma unroll
    for (int o = 16; o > 0; o >>= 1) mx = fmaxf(mx, __shfl_xor_sync(0xffffffffu, mx, o));
    if ((tid & 31) == 0) sm[tid >> 5] = mx;
    __syncthreads();
    mx = sm[0];
    #pragma unroll
    for (int w = 1; w < 8; w++) mx = fmaxf(mx, sm[w]);

    v.x = __expf(v.x - mx); v.y = __expf(v.y - mx);
    v.z = __expf(v.z - mx); v.w = __expf(v.w - mx);
    float s = v.x + v.y + v.z + v.w;
    #pragma unroll
    for (int o = 16; o > 0; o >>= 1) s += __shfl_xor_sync(0xffffffffu, s, o);
    if ((tid & 31) == 0) ssum[tid >> 5] = s;
    __syncthreads();
    s = 0.f;
    #pragma unroll
    for (int w = 0; w < 8; w++) s += ssum[w];

    const float inv = 1.0f / s;
    __nv_bfloat162 p0 = __floats2bfloat162_rn(v.x * inv, v.y * inv);
    __nv_bfloat162 p1 = __floats2bfloat162_rn(v.z * inv, v.w * inv);
    *(__nv_bfloat162*)(q + tid * 4)     = p0;
    *(__nv_bfloat162*)(q + tid * 4 + 2) = p1;
}

// ---------------------------------------------------------------------------
// Launch
// ---------------------------------------------------------------------------
extern "C" void kernel_launch(void* const* d_in, const int* in_sizes, int n_in,
                              void* d_out, int out_size) {
    const float* x     = (const float*)d_in[0];
    const float* gamma = (const float*)d_in[1];
    const float* beta  = (const float*)d_in[2];
    const float* wq = (const float*)d_in[3]; const float* bq = (const float*)d_in[4];
    const float* wk = (const float*)d_in[5]; const float* bk = (const float*)d_in[6];
    const float* wv = (const float*)d_in[7]; const float* bv = (const float*)d_in[8];
    const float* wp = (const float*)d_in[9]; const float* bp = (const float*)d_in[10];

    bf16 *p_xn, *p_q, *p_k, *p_v, *p_o, *p_ah;
    bf16 *p_wq, *p_wk, *p_wv, *p_wp;
    float *p_e;
    cudaGetSymbolAddress((void**)&p_xn, g_xn);
    cudaGetSymbolAddress((void**)&p_q,  g_q);
    cudaGetSymbolAddress((void**)&p_k,  g_k);
    cudaGetSymbolAddress((void**)&p_v,  g_v);
    cudaGetSymbolAddress((void**)&p_o,  g_o);
    cudaGetSymbolAddress((void**)&p_ah, g_ah);
    cudaGetSymbolAddress((void**)&p_e,  g_e);
    cudaGetSymbolAddress((void**)&p_wq, g_wq);
    cudaGetSymbolAddress((void**)&p_wk, g_wk);
    cudaGetSymbolAddress((void**)&p_wv, g_wv);
    cudaGetSymbolAddress((void**)&p_wp, g_wp);

    const size_t sX = (size_t)NC * NHW;
    const size_t sE = (size_t)NHW * NHW;

    wcvt_kernel<<<NC * NC / (256 * 4), 256>>>(wq, wk, wv, wp);
    gn_kernel<<<NB * NG, 256>>>(x, gamma, beta);

    // q, k, v:  C(512x1024) = W(m,k) * xn(k,n) + bias,  bf16 out
    dim3 gc(NHW / 128, NC / 128, NB);
    mm_bf16<false,true,false,true,false><<<gc, 256>>>(p_wq, p_xn, bq, nullptr, p_q,
        NHW, NC, NC, NHW, 0, sX, sX, 1.f);
    mm_bf16<false,true,false,true,false><<<gc, 256>>>(p_wk, p_xn, bk, nullptr, p_k,
        NHW, NC, NC, NHW, 0, sX, sX, 1.f);
    mm_bf16<false,true,false,true,false><<<gc, 256>>>(p_wv, p_xn, bv, nullptr, p_v,
        NHW, NC, NC, NHW, 0, sX, sX, 1.f);

    // energy(1024x1024) = alpha * q^T k  (A (k,m), B (k,n)), f32 out
    dim3 ge(NHW / 128, NHW / 128, NB);
    mm_bf16<true,true,true,false,false><<<ge, 256>>>(p_q, p_k, nullptr, nullptr, p_e,
        NHW, NC, NHW, NHW, sX, sX, sE, 0.04419417382415922f);

    softmax_kernel<<<NB * NHW, 256>>>();

    // O(512x1024) = V(m,k) * attn(n,k),  bf16 out
    mm_bf16<false,false,false,false,false><<<gc, 256>>>(p_v, p_ah, nullptr, nullptr, p_o,
        NHW, NHW, NHW, NHW, sX, sE, sX, 1.f);

    // proj + bias + residual -> f32 d_out
    mm_bf16<false,true,true,true,true><<<gc, 256>>>(p_wp, p_o, bp, x, d_out,
        NHW, NC, NC, NHW, 0, sX, sX, 1.f);
}

// round 11
// speedup vs baseline: 12.0732x; 1.0561x over previous
#include <cuda_runtime.h>
#include <cuda_bf16.h>
#include <cstdint>

#define NB 16
#define NC 512
#define NHW 1024

typedef __nv_bfloat16 bf16;

// Scratch (allocation-free rule: __device__ globals)
__device__ bf16  g_xn  [(size_t)NB * NC * NHW];        // (b, c, hw)
__device__ bf16  g_qkv [(size_t)NB * 3 * NC * NHW];    // (b, [q;k;v] 1536, hw)
__device__ bf16  g_o   [(size_t)NB * NC * NHW];        // (b, c, hw)
__device__ float g_e   [(size_t)NB * NHW * NHW];       // energy f32
__device__ bf16  g_ah  [(size_t)NB * NHW * NHW];       // attn bf16 (i, j)
__device__ bf16  g_wqkv[3 * NC * NC];                  // [wq; wk; wv] (1536, 512)
__device__ bf16  g_wp  [NC * NC];
__device__ float g_bqkv[3 * NC];

// ---------------------------------------------------------------------------
// PTX helpers
// ---------------------------------------------------------------------------
__device__ __forceinline__ void cpasync16(uint32_t smem, const bf16* g) {
    asm volatile("cp.async.cg.shared.global [%0], [%1], 16;\n" :: "r"(smem), "l"(g));
}
__device__ __forceinline__ void cp_commit() { asm volatile("cp.async.commit_group;\n"); }
template<int N> __device__ __forceinline__ void cp_wait() {
    asm volatile("cp.async.wait_group %0;\n" :: "n"(N));
}
__device__ __forceinline__ void ldsm4(uint32_t& r0, uint32_t& r1, uint32_t& r2, uint32_t& r3,
                                      uint32_t a) {
    asm volatile("ldmatrix.sync.aligned.m8n8.x4.shared.b16 {%0,%1,%2,%3}, [%4];"
                 : "=r"(r0), "=r"(r1), "=r"(r2), "=r"(r3) : "r"(a));
}
__device__ __forceinline__ void ldsm4t(uint32_t& r0, uint32_t& r1, uint32_t& r2, uint32_t& r3,
                                       uint32_t a) {
    asm volatile("ldmatrix.sync.aligned.m8n8.x4.trans.shared.b16 {%0,%1,%2,%3}, [%4];"
                 : "=r"(r0), "=r"(r1), "=r"(r2), "=r"(r3) : "r"(a));
}
__device__ __forceinline__ void mma_bf16(float* c, const uint32_t* a, const uint32_t* b) {
    asm volatile(
        "mma.sync.aligned.m16n8k16.row.col.f32.bf16.bf16.f32 "
        "{%0,%1,%2,%3}, {%4,%5,%6,%7}, {%8,%9}, {%0,%1,%2,%3};"
        : "+f"(c[0]), "+f"(c[1]), "+f"(c[2]), "+f"(c[3])
        : "r"(a[0]), "r"(a[1]), "r"(a[2]), "r"(a[3]), "r"(b[0]), "r"(b[1]));
}

// ---------------------------------------------------------------------------
// bf16 GEMM:  C[b](m,n) = alpha * sum_k A(m,k)*B(k,n) [+ bias(m)] [+ R]
//   AKM:  A stored (k,m) m-contiguous (else (m,k) k-contiguous)
//   BKN:  B stored (k,n) n-contiguous (else (n,k) k-contiguous)
// Block 128x128x32, 128 threads, 4 warps in 2x2 of 64x64 tiles, 3-stage
// cp.async, LDSM frags, one sync per K-iter. OUTF: f32 out else bf16.
// ---------------------------------------------------------------------------
template<bool AKM, bool BKN, bool OUTF, bool BIAS, bool RES>
__global__ void __launch_bounds__(128, 2) mm_bf16(
    const bf16* __restrict__ A, const bf16* __restrict__ B,
    const float* __restrict__ bias, const float* __restrict__ R,
    void* __restrict__ C,
    int N, int K, int lda, int ldb,
    size_t sA, size_t sB, size_t sC, float alpha)
{
    __shared__ __align__(16) bf16 As[3][4096];
    __shared__ __align__(16) bf16 Bs[3][4096];

    const int tid  = threadIdx.x;
    const int lane = tid & 31;
    const int warp = tid >> 5;
    const int wm = (warp & 1) * 64;
    const int wn = (warp >> 1) * 64;
    const int g  = lane >> 2, tq = lane & 3;

    const int bz = blockIdx.z;
    const int m0 = blockIdx.y * 128, n0 = blockIdx.x * 128;

    const bf16* Ab = A + (size_t)bz * sA;
    const bf16* Bb = B + (size_t)bz * sB;

    const uint32_t sa_base = (uint32_t)__cvta_generic_to_shared(&As[0][0]);
    const uint32_t sb_base = (uint32_t)__cvta_generic_to_shared(&Bs[0][0]);

    // --- per-lane LDSM byte offsets within one stage buffer ---
    const int mat = lane >> 3, rin = lane & 7;
    uint32_t offA[4][2], offB[4][2];
    #pragma unroll
    for (int mi = 0; mi < 4; mi++)
        #pragma unroll
        for (int kk = 0; kk < 2; kk++) {
            if (!AKM) {
                const int row = wm + mi * 16 + ((mat & 1) << 3) + rin;
                const int c   = kk * 2 + (mat >> 1);
                offA[mi][kk] = row * 64 + ((c ^ ((row >> 1) & 3)) << 4);
            } else {
                const int kr = kk * 16 + ((mat >> 1) << 3) + rin;
                const int cm = (wm + mi * 16 + ((mat & 1) << 3)) >> 3;
                offA[mi][kk] = kr * 256 + ((cm ^ (kr & 7)) << 4);
            }
        }
    #pragma unroll
    for (int ni = 0; ni < 4; ni++)
        #pragma unroll
        for (int kk = 0; kk < 2; kk++) {
            if (!BKN) {
                const int row = wn + ni * 16 + ((mat >> 1) << 3) + rin;
                const int c   = kk * 2 + (mat & 1);
                offB[ni][kk] = row * 64 + ((c ^ ((row >> 1) & 3)) << 4);
            } else {
                const int kr = kk * 16 + ((mat & 1) << 3) + rin;
                const int cn = (wn + ni * 16 + ((mat >> 1) << 3)) >> 3;
                offB[ni][kk] = kr * 256 + ((cn ^ (kr & 7)) << 4);
            }
        }

    const int nk = K / 32;

    auto issue = [&](int t) {
        const int kb = t * 32;
        const uint32_t sa = sa_base + (t % 3) * 8192;
        const uint32_t sb = sb_base + (t % 3) * 8192;
        #pragma unroll
        for (int i = 0; i < 4; i++) {
            const int idx = i * 128 + tid;   // 512 16B-chunks each for A, B
            if (!AKM) {
                const int row = idx >> 2, c = idx & 3;
                cpasync16(sa + row * 64 + ((c ^ ((row >> 1) & 3)) << 4),
                          Ab + (size_t)(m0 + row) * lda + kb + c * 8);
            } else {
                const int kr = idx >> 4, cm = idx & 15;
                cpasync16(sa + kr * 256 + ((cm ^ (kr & 7)) << 4),
                          Ab + (size_t)(kb + kr) * lda + m0 + cm * 8);
            }
            if (!BKN) {
                const int row = idx >> 2, c = idx & 3;
                cpasync16(sb + row * 64 + ((c ^ ((row >> 1) & 3)) << 4),
                          Bb + (size_t)(n0 + row) * ldb + kb + c * 8);
            } else {
                const int kr = idx >> 4, cn = idx & 15;
                cpasync16(sb + kr * 256 + ((cn ^ (kr & 7)) << 4),
                          Bb + (size_t)(kb + kr) * ldb + n0 + cn * 8);
            }
        }
        cp_commit();
    };

    float acc[4][8][4] = {};

    issue(0);
    issue(1);

    for (int t = 0; t < nk; t++) {
        cp_wait<1>();
        __syncthreads();
        if (t + 2 < nk) issue(t + 2); else cp_commit();

        const uint32_t sa = sa_base + (t % 3) * 8192;
        const uint32_t sb = sb_base + (t % 3) * 8192;

        // load ALL fragments for this K-slab (both kk halves) up front
        uint32_t af[2][4][4];
        uint32_t bf[2][8][2];
        #pragma unroll
        for (int kk = 0; kk < 2; kk++) {
            #pragma unroll
            for (int mi = 0; mi < 4; mi++) {
                if (!AKM) ldsm4 (af[kk][mi][0], af[kk][mi][1], af[kk][mi][2], af[kk][mi][3],
                                 sa + offA[mi][kk]);
                else      ldsm4t(af[kk][mi][0], af[kk][mi][1], af[kk][mi][2], af[kk][mi][3],
                                 sa + offA[mi][kk]);
            }
            #pragma unroll
            for (int ni = 0; ni < 4; ni++) {
                uint32_t b0, b1, b2, b3;
                if (!BKN) ldsm4 (b0, b1, b2, b3, sb + offB[ni][kk]);
                else      ldsm4t(b0, b1, b2, b3, sb + offB[ni][kk]);
                bf[kk][ni * 2][0] = b0;     bf[kk][ni * 2][1] = b1;
                bf[kk][ni * 2 + 1][0] = b2; bf[kk][ni * 2 + 1][1] = b3;
            }
        }
        #pragma unroll
        for (int kk = 0; kk < 2; kk++)
            #pragma unroll
            for (int mi = 0; mi < 4; mi++)
                #pragma unroll
                for (int nj = 0; nj < 8; nj++)
                    mma_bf16(acc[mi][nj], af[kk][mi], bf[kk][nj]);
    }

    // ---------------- epilogue ----------------
    const float* Rb = RES ? R + (size_t)bz * sC : nullptr;
    #pragma unroll
    for (int mi = 0; mi < 4; mi++) {
        const int r0 = m0 + wm + mi * 16 + g;
        const int r1 = r0 + 8;
        const float bv0 = BIAS ? bias[r0] : 0.f;
        const float bv1 = BIAS ? bias[r1] : 0.f;
        #pragma unroll
        for (int nj = 0; nj < 8; nj++) {
            const int col = n0 + wn + nj * 8 + tq * 2;
            float v00 = acc[mi][nj][0] * alpha + bv0;
            float v01 = acc[mi][nj][1] * alpha + bv0;
            float v10 = acc[mi][nj][2] * alpha + bv1;
            float v11 = acc[mi][nj][3] * alpha + bv1;
            if (RES) {
                float2 x0 = *(const float2*)&Rb[(size_t)r0 * N + col];
                float2 x1 = *(const float2*)&Rb[(size_t)r1 * N + col];
                v00 += x0.x; v01 += x0.y; v10 += x1.x; v11 += x1.y;
            }
            if (OUTF) {
                float* Cb = (float*)C + (size_t)bz * sC;
                *(float2*)&Cb[(size_t)r0 * N + col] = make_float2(v00, v01);
                *(float2*)&Cb[(size_t)r1 * N + col] = make_float2(v10, v11);
            } else {
                bf16* Cb = (bf16*)C + (size_t)bz * sC;
                *(__nv_bfloat162*)&Cb[(size_t)r0 * N + col] = __floats2bfloat162_rn(v00, v01);
                *(__nv_bfloat162*)&Cb[(size_t)r1 * N + col] = __floats2bfloat162_rn(v10, v11);
            }
        }
    }
}

// ---------------------------------------------------------------------------
// Weight conversion: wq/wk/wv -> g_wqkv (concat), wp -> g_wp, biases -> g_bqkv
// ---------------------------------------------------------------------------
__global__ void __launch_bounds__(256) wcvt_kernel(
    const float* __restrict__ wq, const float* __restrict__ wk,
    const float* __restrict__ wv, const float* __restrict__ wp,
    const float* __restrict__ bq, const float* __restrict__ bk,
    const float* __restrict__ bv)
{
    const int i = (blockIdx.x * 256 + threadIdx.x) * 4;
    if (i < NC * NC) {
        const float* src[4] = {wq, wk, wv, wp};
        bf16* dst[4] = {g_wqkv, g_wqkv + NC * NC, g_wqkv + 2 * NC * NC, g_wp};
        #pragma unroll
        for (int j = 0; j < 4; j++) {
            float4 v = *(const float4*)(src[j] + i);
            *(__nv_bfloat162*)(dst[j] + i)     = __floats2bfloat162_rn(v.x, v.y);
            *(__nv_bfloat162*)(dst[j] + i + 2) = __floats2bfloat162_rn(v.z, v.w);
        }
    }
    const int t = blockIdx.x * 256 + threadIdx.x;
    if (t < NC) {
        g_bqkv[t]          = bq[t];
        g_bqkv[t + NC]     = bk[t];
        g_bqkv[t + 2 * NC] = bv[t];
    }
}

// ---------------------------------------------------------------------------
// GroupNorm: one block per (batch, group). Writes bf16 xn (c, hw).
// ---------------------------------------------------------------------------
__global__ void __launch_bounds__(256) gn_kernel(const float* __restrict__ x,
                                                 const float* __restrict__ gamma,
                                                 const float* __restrict__ beta) {
    const int bg = blockIdx.x;
    const int b = bg >> 5, g = bg & 31;
    const size_t base = ((size_t)b * NC + (size_t)g * 16) * NHW;
    const float* xp = x + base;
    bf16* op = g_xn + base;
    const int N = 16 * NHW;

    float s = 0.f, ss = 0.f;
    for (int i = threadIdx.x * 4; i < N; i += 256 * 4) {
        float4 v = *(const float4*)(xp + i);
        s  += v.x + v.y + v.z + v.w;
        ss += v.x*v.x + v.y*v.y + v.z*v.z + v.w*v.w;
    }
    __shared__ float rs[8], rq[8];
    #pragma unroll
    for (int o = 16; o > 0; o >>= 1) {
        s  += __shfl_xor_sync(0xffffffffu, s,  o);
        ss += __shfl_xor_sync(0xffffffffu, ss, o);
    }
    if ((threadIdx.x & 31) == 0) { rs[threadIdx.x >> 5] = s; rq[threadIdx.x >> 5] = ss; }
    __syncthreads();
    s = 0.f; ss = 0.f;
    #pragma unroll
    for (int w = 0; w < 8; w++) { s += rs[w]; ss += rq[w]; }

    const float mean = s / (float)N;
    const float var  = ss / (float)N - mean * mean;
    const float rstd = rsqrtf(var + 1e-6f);

    for (int i = threadIdx.x * 4; i < N; i += 256 * 4) {
        const int c = g * 16 + (i >> 10);
        const float gm = gamma[c] * rstd;
        const float bt = beta[c] - mean * gm;
        float4 v = *(const float4*)(xp + i);
        *(__nv_bfloat162*)(op + i)     = __floats2bfloat162_rn(v.x * gm + bt, v.y * gm + bt);
        *(__nv_bfloat162*)(op + i + 2) = __floats2bfloat162_rn(v.z * gm + bt, v.w * gm + bt);
    }
}

// ---------------------------------------------------------------------------
// Softmax rows of g_e (f32, 1024 wide) -> g_ah (bf16). One block per row.
// ---------------------------------------------------------------------------
__global__ void __launch_bounds__(256) softmax_kernel() {
    const size_t row = blockIdx.x;
    const float* p = g_e + row * NHW;
    bf16* q = g_ah + row * NHW;
    const int tid = threadIdx.x;

    float4 v = ((const float4*)p)[tid];
    float mx = fmaxf(fmaxf(v.x, v.y), fmaxf(v.z, v.w));
    __shared__ float sm[8], ssum[8];
    #pragma unroll
    for (int o = 16; o > 0; o >>= 1) mx = fmaxf(mx, __shfl_xor_sync(0xffffffffu, mx, o));
    if ((tid & 31) == 0) sm[tid >> 5] = mx;
    __syncthreads();
    mx = sm[0];
    #pragma unroll
    for (int w = 1; w < 8; w++) mx = fmaxf(mx, sm[w]);

    v.x = __expf(v.x - mx); v.y = __expf(v.y - mx);
    v.z = __expf(v.z - mx); v.w = __expf(v.w - mx);
    float s = v.x + v.y + v.z + v.w;
    #pragma unroll
    for (int o = 16; o > 0; o >>= 1) s += __shfl_xor_sync(0xffffffffu, s, o);
    if ((tid & 31) == 0) ssum[tid >> 5] = s;
    __syncthreads();
    s = 0.f;
    #pragma unroll
    for (int w = 0; w < 8; w++) s += ssum[w];

    const float inv = 1.0f / s;
    *(__nv_bfloat162*)(q + tid * 4)     = __floats2bfloat162_rn(v.x * inv, v.y * inv);
    *(__nv_bfloat162*)(q + tid * 4 + 2) = __floats2bfloat162_rn(v.z * inv, v.w * inv);
}

// ---------------------------------------------------------------------------
// Launch
// ---------------------------------------------------------------------------
extern "C" void kernel_launch(void* const* d_in, const int* in_sizes, int n_in,
                              void* d_out, int out_size) {
    const float* x     = (const float*)d_in[0];
    const float* gamma = (const float*)d_in[1];
    const float* beta  = (const float*)d_in[2];
    const float* wq = (const float*)d_in[3]; const float* bq = (const float*)d_in[4];
    const float* wk = (const float*)d_in[5]; const float* bk = (const float*)d_in[6];
    const float* wv = (const float*)d_in[7]; const float* bv = (const float*)d_in[8];
    const float* wp = (const float*)d_in[9]; const float* bp = (const float*)d_in[10];

    bf16 *p_xn, *p_qkv, *p_o, *p_ah, *p_wqkv, *p_wp;
    float *p_e, *p_bqkv;
    cudaGetSymbolAddress((void**)&p_xn,   g_xn);
    cudaGetSymbolAddress((void**)&p_qkv,  g_qkv);
    cudaGetSymbolAddress((void**)&p_o,    g_o);
    cudaGetSymbolAddress((void**)&p_ah,   g_ah);
    cudaGetSymbolAddress((void**)&p_e,    g_e);
    cudaGetSymbolAddress((void**)&p_wqkv, g_wqkv);
    cudaGetSymbolAddress((void**)&p_wp,   g_wp);
    cudaGetSymbolAddress((void**)&p_bqkv, g_bqkv);

    const size_t sX   = (size_t)NC * NHW;        // per-batch (c, hw)
    const size_t sQKV = (size_t)3 * NC * NHW;    // per-batch (1536, hw)
    const size_t sE   = (size_t)NHW * NHW;

    const bf16* p_q = p_qkv;                 // rows 0..511    of (1536, hw)
    const bf16* p_k = p_qkv + NC * NHW;      // rows 512..1023
    const bf16* p_v = p_qkv + 2 * NC * NHW;  // rows 1024..1535

    wcvt_kernel<<<NC * NC / (256 * 4), 256>>>(wq, wk, wv, wp, bq, bk, bv);
    gn_kernel<<<NB * 32, 256>>>(x, gamma, beta);

    // fused qkv: (1536 x 1024) = Wqkv(m,k) . xn(k,n) + bias -> g_qkv, bf16
    mm_bf16<false,true,false,true,false><<<dim3(NHW/128, 3*NC/128, NB), 128>>>(
        p_wqkv, p_xn, p_bqkv, nullptr, p_qkv, NHW, NC, NC, NHW, 0, sX, sQKV, 1.f);

    // energy(1024x1024) = alpha * q^T k  (A (k,m), B (k,n)), f32 out
    mm_bf16<true,true,true,false,false><<<dim3(NHW/128, NHW/128, NB), 128>>>(
        p_q, p_k, nullptr, nullptr, p_e, NHW, NC, NHW, NHW, sQKV, sQKV, sE,
        0.04419417382415922f);

    softmax_kernel<<<NB * NHW, 256>>>();

    // O(512x1024) = V(m,k) . attn(n,k), bf16 out
    mm_bf16<false,false,false,false,false><<<dim3(NHW/128, NC/128, NB), 128>>>(
        p_v, p_ah, nullptr, nullptr, p_o, NHW, NHW, NHW, NHW, sQKV, sE, sX, 1.f);

    // proj + bias + residual -> f32 d_out
    mm_bf16<false,true,true,true,true><<<dim3(NHW/128, NC/128, NB), 128>>>(
        p_wp, p_o, bp, x, d_out, NHW, NC, NC, NHW, 0, sX, sX, 1.f);
}

// round 15
// speedup vs baseline: 12.5147x; 1.0366x over previous
#include <cuda_runtime.h>
#include <cuda_bf16.h>
#include <cstdint>

#define NB 16
#define NC 512
#define NHW 1024

typedef __nv_bfloat16 bf16;

// Scratch (allocation-free rule: __device__ globals)
__device__ bf16  g_xn  [(size_t)NB * NC * NHW];        // (b, c, hw)
__device__ bf16  g_qkv [(size_t)NB * 3 * NC * NHW];    // (b, [q;k;v] 1536, hw)
__device__ bf16  g_o   [(size_t)NB * NC * NHW];        // (b, c, hw)
__device__ float g_e   [(size_t)NB * NHW * NHW];       // energy f32
__device__ bf16  g_ah  [(size_t)NB * NHW * NHW];       // attn bf16 (i, j)
__device__ bf16  g_wqkv[3 * NC * NC];                  // [wq; wk; wv] (1536, 512)
__device__ bf16  g_wp  [NC * NC];
__device__ float g_bqkv[3 * NC];

// ---------------------------------------------------------------------------
// PTX helpers
// ---------------------------------------------------------------------------
__device__ __forceinline__ void cpasync16(uint32_t smem, const bf16* g) {
    asm volatile("cp.async.cg.shared.global [%0], [%1], 16;\n" :: "r"(smem), "l"(g));
}
__device__ __forceinline__ void cp_commit() { asm volatile("cp.async.commit_group;\n"); }
template<int N> __device__ __forceinline__ void cp_wait() {
    asm volatile("cp.async.wait_group %0;\n" :: "n"(N));
}
__device__ __forceinline__ void ldsm4(uint32_t& r0, uint32_t& r1, uint32_t& r2, uint32_t& r3,
                                      uint32_t a) {
    asm volatile("ldmatrix.sync.aligned.m8n8.x4.shared.b16 {%0,%1,%2,%3}, [%4];"
                 : "=r"(r0), "=r"(r1), "=r"(r2), "=r"(r3) : "r"(a));
}
__device__ __forceinline__ void ldsm4t(uint32_t& r0, uint32_t& r1, uint32_t& r2, uint32_t& r3,
                                       uint32_t a) {
    asm volatile("ldmatrix.sync.aligned.m8n8.x4.trans.shared.b16 {%0,%1,%2,%3}, [%4];"
                 : "=r"(r0), "=r"(r1), "=r"(r2), "=r"(r3) : "r"(a));
}
__device__ __forceinline__ void mma_bf16(float* c, const uint32_t* a, const uint32_t* b) {
    asm volatile(
        "mma.sync.aligned.m16n8k16.row.col.f32.bf16.bf16.f32 "
        "{%0,%1,%2,%3}, {%4,%5,%6,%7}, {%8,%9}, {%0,%1,%2,%3};"
        : "+f"(c[0]), "+f"(c[1]), "+f"(c[2]), "+f"(c[3])
        : "r"(a[0]), "r"(a[1]), "r"(a[2]), "r"(a[3]), "r"(b[0]), "r"(b[1]));
}

// ---------------------------------------------------------------------------
// bf16 GEMM:  C[b](m,n) = alpha * sum_k A(m,k)*B(k,n) [+ bias(m)] [+ R]
//   AKM:  A stored (k,m) m-contiguous (else (m,k) k-contiguous)
//   BKN:  B stored (k,n) n-contiguous (else (n,k) k-contiguous)
// Block 128x128x64, 128 threads, 4 warps of 64x64, 2-stage cp.async
// double buffer (64KB dynamic smem), fragment kk ping-pong, 1 sync/K-iter.
// Smem rows: 128B rows (m,k)/(n,k): chunk c ^ (row & 7)
//            256B rows (k,m)/(k,n): chunk c ^ (krow & 7), kk step = +4096B
// ---------------------------------------------------------------------------
template<bool AKM, bool BKN, bool OUTF, bool BIAS, bool RES>
__global__ void __launch_bounds__(128, 2) mm_bf16(
    const bf16* __restrict__ A, const bf16* __restrict__ B,
    const float* __restrict__ bias, const float* __restrict__ R,
    void* __restrict__ C,
    int N, int K, int lda, int ldb,
    size_t sA, size_t sB, size_t sC, float alpha)
{
    extern __shared__ __align__(16) bf16 dsm[];

    const int tid  = threadIdx.x;
    const int lane = tid & 31;
    const int warp = tid >> 5;
    const int wm = (warp & 1) * 64;
    const int wn = (warp >> 1) * 64;
    const int g  = lane >> 2, tq = lane & 3;
    const int mat = lane >> 3, rin = lane & 7;

    const int bz = blockIdx.z;
    const int m0 = blockIdx.y * 128, n0 = blockIdx.x * 128;

    const bf16* Ab = A + (size_t)bz * sA;
    const bf16* Bb = B + (size_t)bz * sB;

    const uint32_t s_base = (uint32_t)__cvta_generic_to_shared(dsm);
    // A stages: [0, 16K), [16K, 32K).  B stages: [32K, 48K), [48K, 64K).

    // --- per-lane LDSM address components ---
    uint32_t aB[4], aX[4];
    const int cselA = mat >> 1;            // used when !AKM
    #pragma unroll
    for (int mi = 0; mi < 4; mi++) {
        if (!AKM) {
            const int row = wm + mi * 16 + ((mat & 1) << 3) + rin;
            aB[mi] = row * 128; aX[mi] = row & 7;
        } else {
            const int krb = ((mat >> 1) << 3) + rin;
            const int cm = (wm + mi * 16 + ((mat & 1) << 3)) >> 3;
            aB[mi] = krb * 256 + ((cm ^ (krb & 7)) << 4); aX[mi] = 0;
        }
    }
    uint32_t bB[4], bX[4];
    const int cselB = mat & 1;             // used when !BKN
    #pragma unroll
    for (int ni = 0; ni < 4; ni++) {
        if (!BKN) {
            const int row = wn + ni * 16 + ((mat >> 1) << 3) + rin;
            bB[ni] = row * 128; bX[ni] = row & 7;
        } else {
            const int krb = ((mat & 1) << 3) + rin;
            const int cn = (wn + ni * 16 + ((mat >> 1) << 3)) >> 3;
            bB[ni] = krb * 256 + ((cn ^ (krb & 7)) << 4); bX[ni] = 0;
        }
    }

    const int nk = K >> 6;

    auto issue = [&](int t) {
        const int kb = t << 6;
        const uint32_t sa = s_base + (t & 1) * 16384;
        const uint32_t sb = s_base + 32768 + (t & 1) * 16384;
        #pragma unroll
        for (int i = 0; i < 8; i++) {
            const int idx = i * 128 + tid;   // 1024 16B-chunks for A
            if (!AKM) {
                const int row = idx >> 3, c = idx & 7;
                cpasync16(sa + row * 128 + ((c ^ (row & 7)) << 4),
                          Ab + (size_t)(m0 + row) * lda + kb + c * 8);
            } else {
                const int kr = idx >> 4, cm = idx & 15;
                cpasync16(sa + kr * 256 + ((cm ^ (kr & 7)) << 4),
                          Ab + (size_t)(kb + kr) * lda + m0 + cm * 8);
            }
        }
        #pragma unroll
        for (int i = 0; i < 8; i++) {
            const int idx = i * 128 + tid;   // 1024 16B-chunks for B
            if (!BKN) {
                const int row = idx >> 3, c = idx & 7;
                cpasync16(sb + row * 128 + ((c ^ (row & 7)) << 4),
                          Bb + (size_t)(n0 + row) * ldb + kb + c * 8);
            } else {
                const int kr = idx >> 4, cn = idx & 15;
                cpasync16(sb + kr * 256 + ((cn ^ (kr & 7)) << 4),
                          Bb + (size_t)(kb + kr) * ldb + n0 + cn * 8);
            }
        }
        cp_commit();
    };

    float acc[4][8][4] = {};
    uint32_t af[2][4][4];
    uint32_t bfr[2][8][2];

    issue(0);

    for (int t = 0; t < nk; t++) {
        cp_wait<0>();
        __syncthreads();
        if (t + 1 < nk) issue(t + 1);

        const uint32_t sa = s_base + (t & 1) * 16384;
        const uint32_t sb = s_base + 32768 + (t & 1) * 16384;

        auto ldA = [&](int kk, int f) {
            #pragma unroll
            for (int mi = 0; mi < 4; mi++) {
                const uint32_t addr = AKM
                    ? sa + aB[mi] + kk * 4096
                    : sa + aB[mi] + ((((kk << 1) | cselA) ^ aX[mi]) << 4);
                if (!AKM) ldsm4 (af[f][mi][0], af[f][mi][1], af[f][mi][2], af[f][mi][3], addr);
                else      ldsm4t(af[f][mi][0], af[f][mi][1], af[f][mi][2], af[f][mi][3], addr);
            }
        };
        auto ldB = [&](int kk, int f) {
            #pragma unroll
            for (int ni = 0; ni < 4; ni++) {
                const uint32_t addr = BKN
                    ? sb + bB[ni] + kk * 4096
                    : sb + bB[ni] + ((((kk << 1) | cselB) ^ bX[ni]) << 4);
                uint32_t b0, b1, b2, b3;
                if (!BKN) ldsm4 (b0, b1, b2, b3, addr);
                else      ldsm4t(b0, b1, b2, b3, addr);
                bfr[f][ni * 2][0] = b0;     bfr[f][ni * 2][1] = b1;
                bfr[f][ni * 2 + 1][0] = b2; bfr[f][ni * 2 + 1][1] = b3;
            }
        };

        ldA(0, 0); ldB(0, 0);
        #pragma unroll
        for (int kk = 0; kk < 4; kk++) {
            const int cur = kk & 1;
            if (kk < 3) { ldA(kk + 1, cur ^ 1); ldB(kk + 1, cur ^ 1); }
            #pragma unroll
            for (int mi = 0; mi < 4; mi++)
                #pragma unroll
                for (int nj = 0; nj < 8; nj++)
                    mma_bf16(acc[mi][nj], af[cur][mi], bfr[cur][nj]);
        }
    }

    // ---------------- epilogue ----------------
    const float* Rb = RES ? R + (size_t)bz * sC : nullptr;
    #pragma unroll
    for (int mi = 0; mi < 4; mi++) {
        const int r0 = m0 + wm + mi * 16 + g;
        const int r1 = r0 + 8;
        const float bv0 = BIAS ? bias[r0] : 0.f;
        const float bv1 = BIAS ? bias[r1] : 0.f;
        #pragma unroll
        for (int nj = 0; nj < 8; nj++) {
            const int col = n0 + wn + nj * 8 + tq * 2;
            float v00 = acc[mi][nj][0] * alpha + bv0;
            float v01 = acc[mi][nj][1] * alpha + bv0;
            float v10 = acc[mi][nj][2] * alpha + bv1;
            float v11 = acc[mi][nj][3] * alpha + bv1;
            if (RES) {
                float2 x0 = *(const float2*)&Rb[(size_t)r0 * N + col];
                float2 x1 = *(const float2*)&Rb[(size_t)r1 * N + col];
                v00 += x0.x; v01 += x0.y; v10 += x1.x; v11 += x1.y;
            }
            if (OUTF) {
                float* Cb = (float*)C + (size_t)bz * sC;
                *(float2*)&Cb[(size_t)r0 * N + col] = make_float2(v00, v01);
                *(float2*)&Cb[(size_t)r1 * N + col] = make_float2(v10, v11);
            } else {
                bf16* Cb = (bf16*)C + (size_t)bz * sC;
                *(__nv_bfloat162*)&Cb[(size_t)r0 * N + col] = __floats2bfloat162_rn(v00, v01);
                *(__nv_bfloat162*)&Cb[(size_t)r1 * N + col] = __floats2bfloat162_rn(v10, v11);
            }
        }
    }
}

// ---------------------------------------------------------------------------
// Weight conversion: wq/wk/wv -> g_wqkv (concat), wp -> g_wp, biases -> g_bqkv
// ---------------------------------------------------------------------------
__global__ void __launch_bounds__(256) wcvt_kernel(
    const float* __restrict__ wq, const float* __restrict__ wk,
    const float* __restrict__ wv, const float* __restrict__ wp,
    const float* __restrict__ bq, const float* __restrict__ bk,
    const float* __restrict__ bv)
{
    const int i = (blockIdx.x * 256 + threadIdx.x) * 4;
    if (i < NC * NC) {
        const float* src[4] = {wq, wk, wv, wp};
        bf16* dst[4] = {g_wqkv, g_wqkv + NC * NC, g_wqkv + 2 * NC * NC, g_wp};
        #pragma unroll
        for (int j = 0; j < 4; j++) {
            float4 v = *(const float4*)(src[j] + i);
            *(__nv_bfloat162*)(dst[j] + i)     = __floats2bfloat162_rn(v.x, v.y);
            *(__nv_bfloat162*)(dst[j] + i + 2) = __floats2bfloat162_rn(v.z, v.w);
        }
    }
    const int t = blockIdx.x * 256 + threadIdx.x;
    if (t < NC) {
        g_bqkv[t]          = bq[t];
        g_bqkv[t + NC]     = bk[t];
        g_bqkv[t + 2 * NC] = bv[t];
    }
}

// ---------------------------------------------------------------------------
// GroupNorm: one block per (batch, group). Writes bf16 xn (c, hw).
// ---------------------------------------------------------------------------
__global__ void __launch_bounds__(256) gn_kernel(const float* __restrict__ x,
                                                 const float* __restrict__ gamma,
                                                 const float* __restrict__ beta) {
    const int bg = blockIdx.x;
    const int b = bg >> 5, g = bg & 31;
    const size_t base = ((size_t)b * NC + (size_t)g * 16) * NHW;
    const float* xp = x + base;
    bf16* op = g_xn + base;
    const int N = 16 * NHW;

    float s = 0.f, ss = 0.f;
    for (int i = threadIdx.x * 4; i < N; i += 256 * 4) {
        float4 v = *(const float4*)(xp + i);
        s  += v.x + v.y + v.z + v.w;
        ss += v.x*v.x + v.y*v.y + v.z*v.z + v.w*v.w;
    }
    __shared__ float rs[8], rq[8];
    #pragma unroll
    for (int o = 16; o > 0; o >>= 1) {
        s  += __shfl_xor_sync(0xffffffffu, s,  o);
        ss += __shfl_xor_sync(0xffffffffu, ss, o);
    }
    if ((threadIdx.x & 31) == 0) { rs[threadIdx.x >> 5] = s; rq[threadIdx.x >> 5] = ss; }
    __syncthreads();
    s = 0.f; ss = 0.f;
    #pragma unroll
    for (int w = 0; w < 8; w++) { s += rs[w]; ss += rq[w]; }

    const float mean = s / (float)N;
    const float var  = ss / (float)N - mean * mean;
    const float rstd = rsqrtf(var + 1e-6f);

    for (int i = threadIdx.x * 4; i < N; i += 256 * 4) {
        const int c = g * 16 + (i >> 10);
        const float gm = gamma[c] * rstd;
        const float bt = beta[c] - mean * gm;
        float4 v = *(const float4*)(xp + i);
        *(__nv_bfloat162*)(op + i)     = __floats2bfloat162_rn(v.x * gm + bt, v.y * gm + bt);
        *(__nv_bfloat162*)(op + i + 2) = __floats2bfloat162_rn(v.z * gm + bt, v.w * gm + bt);
    }
}

// ---------------------------------------------------------------------------
// Softmax rows of g_e (f32, 1024 wide) -> g_ah (bf16). One block per row.
// ---------------------------------------------------------------------------
__global__ void __launch_bounds__(256) softmax_kernel() {
    const size_t row = blockIdx.x;
    const float* p = g_e + row * NHW;
    bf16* q = g_ah + row * NHW;
    const int tid = threadIdx.x;

    float4 v = ((const float4*)p)[tid];
    float mx = fmaxf(fmaxf(v.x, v.y), fmaxf(v.z, v.w));
    __shared__ float sm[8], ssum[8];
    #pragma unroll
    for (int o = 16; o > 0; o >>= 1) mx = fmaxf(mx, __shfl_xor_sync(0xffffffffu, mx, o));
    if ((tid & 31) == 0) sm[tid >> 5] = mx;
    __syncthreads();
    mx = sm[0];
    #pragma unroll
    for (int w = 1; w < 8; w++) mx = fmaxf(mx, sm[w]);

    v.x = __expf(v.x - mx); v.y = __expf(v.y - mx);
    v.z = __expf(v.z - mx); v.w = __expf(v.w - mx);
    float s = v.x + v.y + v.z + v.w;
    #pragma unroll
    for (int o = 16; o > 0; o >>= 1) s += __shfl_xor_sync(0xffffffffu, s, o);
    if ((tid & 31) == 0) ssum[tid >> 5] = s;
    __syncthreads();
    s = 0.f;
    #pragma unroll
    for (int w = 0; w < 8; w++) s += ssum[w];

    const float inv = 1.0f / s;
    *(__nv_bfloat162*)(q + tid * 4)     = __floats2bfloat162_rn(v.x * inv, v.y * inv);
    *(__nv_bfloat162*)(q + tid * 4 + 2) = __floats2bfloat162_rn(v.z * inv, v.w * inv);
}

// ---------------------------------------------------------------------------
// Launch
// ---------------------------------------------------------------------------
#define SMEM_DYN 65536

extern "C" void kernel_launch(void* const* d_in, const int* in_sizes, int n_in,
                              void* d_out, int out_size) {
    const float* x     = (const float*)d_in[0];
    const float* gamma = (const float*)d_in[1];
    const float* beta  = (const float*)d_in[2];
    const float* wq = (const float*)d_in[3]; const float* bq = (const float*)d_in[4];
    const float* wk = (const float*)d_in[5]; const float* bk = (const float*)d_in[6];
    const float* wv = (const float*)d_in[7]; const float* bv = (const float*)d_in[8];
    const float* wp = (const float*)d_in[9]; const float* bp = (const float*)d_in[10];

    bf16 *p_xn, *p_qkv, *p_o, *p_ah, *p_wqkv, *p_wp;
    float *p_e, *p_bqkv;
    cudaGetSymbolAddress((void**)&p_xn,   g_xn);
    cudaGetSymbolAddress((void**)&p_qkv,  g_qkv);
    cudaGetSymbolAddress((void**)&p_o,    g_o);
    cudaGetSymbolAddress((void**)&p_ah,   g_ah);
    cudaGetSymbolAddress((void**)&p_e,    g_e);
    cudaGetSymbolAddress((void**)&p_wqkv, g_wqkv);
    cudaGetSymbolAddress((void**)&p_wp,   g_wp);
    cudaGetSymbolAddress((void**)&p_bqkv, g_bqkv);

    cudaFuncSetAttribute(mm_bf16<false,true,false,true,false>,
                         cudaFuncAttributeMaxDynamicSharedMemorySize, SMEM_DYN);
    cudaFuncSetAttribute(mm_bf16<true,true,true,false,false>,
                         cudaFuncAttributeMaxDynamicSharedMemorySize, SMEM_DYN);
    cudaFuncSetAttribute(mm_bf16<false,false,false,false,false>,
                         cudaFuncAttributeMaxDynamicSharedMemorySize, SMEM_DYN);
    cudaFuncSetAttribute(mm_bf16<false,true,true,true,true>,
                         cudaFuncAttributeMaxDynamicSharedMemorySize, SMEM_DYN);

    const size_t sX   = (size_t)NC * NHW;        // per-batch (c, hw)
    const size_t sQKV = (size_t)3 * NC * NHW;    // per-batch (1536, hw)
    const size_t sE   = (size_t)NHW * NHW;

    const bf16* p_q = p_qkv;                 // rows 0..511    of (1536, hw)
    const bf16* p_k = p_qkv + NC * NHW;      // rows 512..1023
    const bf16* p_v = p_qkv + 2 * NC * NHW;  // rows 1024..1535

    wcvt_kernel<<<NC * NC / (256 * 4), 256>>>(wq, wk, wv, wp, bq, bk, bv);
    gn_kernel<<<NB * 32, 256>>>(x, gamma, beta);

    // fused qkv: (1536 x 1024) = Wqkv(m,k) . xn(k,n) + bias -> g_qkv, bf16
    mm_bf16<false,true,false,true,false><<<dim3(NHW/128, 3*NC/128, NB), 128, SMEM_DYN>>>(
        p_wqkv, p_xn, p_bqkv, nullptr, p_qkv, NHW, NC, NC, NHW, 0, sX, sQKV, 1.f);

    // energy(1024x1024) = alpha * q^T k  (A (k,m), B (k,n)), f32 out
    mm_bf16<true,true,true,false,false><<<dim3(NHW/128, NHW/128, NB), 128, SMEM_DYN>>>(
        p_q, p_k, nullptr, nullptr, p_e, NHW, NC, NHW, NHW, sQKV, sQKV, sE,
        0.04419417382415922f);

    softmax_kernel<<<NB * NHW, 256>>>();

    // O(512x1024) = V(m,k) . attn(n,k), bf16 out
    mm_bf16<false,false,false,false,false><<<dim3(NHW/128, NC/128, NB), 128, SMEM_DYN>>>(
        p_v, p_ah, nullptr, nullptr, p_o, NHW, NHW, NHW, NHW, sQKV, sE, sX, 1.f);

    // proj + bias + residual -> f32 d_out
    mm_bf16<false,true,true,true,true><<<dim3(NHW/128, NC/128, NB), 128, SMEM_DYN>>>(
        p_wp, p_o, bp, x, d_out, NHW, NC, NC, NHW, 0, sX, sX, 1.f);
}

// round 16
// speedup vs baseline: 12.7174x; 1.0162x over previous
#include <cuda_runtime.h>
#include <cuda_bf16.h>
#include <cstdint>

#define NB 16
#define NC 512
#define NHW 1024

typedef __nv_bfloat16 bf16;

// Scratch (allocation-free rule: __device__ globals)
__device__ bf16  g_xn  [(size_t)NB * NC * NHW];        // (b, c, hw)
__device__ bf16  g_qkv [(size_t)NB * 3 * NC * NHW];    // (b, [q;k;v] 1536, hw)
__device__ bf16  g_o   [(size_t)NB * NC * NHW];        // (b, c, hw)
__device__ float g_e   [(size_t)NB * NHW * NHW];       // energy f32
__device__ bf16  g_ah  [(size_t)NB * NHW * NHW];       // attn bf16 (i, j)
__device__ bf16  g_wqkv[3 * NC * NC];                  // [wq; wk; wv] (1536, 512)
__device__ bf16  g_wp  [NC * NC];
__device__ float g_bqkv[3 * NC];

// ---------------------------------------------------------------------------
// PTX helpers
// ---------------------------------------------------------------------------
__device__ __forceinline__ void cpasync16(uint32_t smem, const bf16* g) {
    asm volatile("cp.async.cg.shared.global [%0], [%1], 16;\n" :: "r"(smem), "l"(g));
}
__device__ __forceinline__ void cp_commit() { asm volatile("cp.async.commit_group;\n"); }
template<int N> __device__ __forceinline__ void cp_wait() {
    asm volatile("cp.async.wait_group %0;\n" :: "n"(N));
}
__device__ __forceinline__ void ldsm4(uint32_t& r0, uint32_t& r1, uint32_t& r2, uint32_t& r3,
                                      uint32_t a) {
    asm volatile("ldmatrix.sync.aligned.m8n8.x4.shared.b16 {%0,%1,%2,%3}, [%4];"
                 : "=r"(r0), "=r"(r1), "=r"(r2), "=r"(r3) : "r"(a));
}
__device__ __forceinline__ void ldsm4t(uint32_t& r0, uint32_t& r1, uint32_t& r2, uint32_t& r3,
                                       uint32_t a) {
    asm volatile("ldmatrix.sync.aligned.m8n8.x4.trans.shared.b16 {%0,%1,%2,%3}, [%4];"
                 : "=r"(r0), "=r"(r1), "=r"(r2), "=r"(r3) : "r"(a));
}
__device__ __forceinline__ void mma_bf16(float* c, const uint32_t* a, const uint32_t* b) {
    asm volatile(
        "mma.sync.aligned.m16n8k16.row.col.f32.bf16.bf16.f32 "
        "{%0,%1,%2,%3}, {%4,%5,%6,%7}, {%8,%9}, {%0,%1,%2,%3};"
        : "+f"(c[0]), "+f"(c[1]), "+f"(c[2]), "+f"(c[3])
        : "r"(a[0]), "r"(a[1]), "r"(a[2]), "r"(a[3]), "r"(b[0]), "r"(b[1]));
}

// ---------------------------------------------------------------------------
// bf16 GEMM:  C[b](m,n) = alpha * sum_k A(m,k)*B(k,n) [+ bias(m)] [+ R]
//   AKM:  A stored (k,m) m-contiguous (else (m,k) k-contiguous)
//   BKN:  B stored (k,n) n-contiguous (else (n,k) k-contiguous)
// Block 128x128x64, 128 threads, 4 warps of 64x64, 3-stage cp.async
// pipeline (96KB dynamic smem), fragment kk ping-pong, 1 sync/K-iter.
// Smem rows: 128B rows (m,k)/(n,k): chunk c ^ (row & 7)
//            256B rows (k,m)/(k,n): chunk c ^ (krow & 7), kk step = +4096B
// ---------------------------------------------------------------------------
template<bool AKM, bool BKN, bool OUTF, bool BIAS, bool RES>
__global__ void __launch_bounds__(128, 2) mm_bf16(
    const bf16* __restrict__ A, const bf16* __restrict__ B,
    const float* __restrict__ bias, const float* __restrict__ R,
    void* __restrict__ C,
    int N, int K, int lda, int ldb,
    size_t sA, size_t sB, size_t sC, float alpha)
{
    extern __shared__ __align__(16) bf16 dsm[];

    const int tid  = threadIdx.x;
    const int lane = tid & 31;
    const int warp = tid >> 5;
    const int wm = (warp & 1) * 64;
    const int wn = (warp >> 1) * 64;
    const int g  = lane >> 2, tq = lane & 3;
    const int mat = lane >> 3, rin = lane & 7;

    const int bz = blockIdx.z;
    const int m0 = blockIdx.y * 128, n0 = blockIdx.x * 128;

    const bf16* Ab = A + (size_t)bz * sA;
    const bf16* Bb = B + (size_t)bz * sB;

    const uint32_t s_base = (uint32_t)__cvta_generic_to_shared(dsm);
    // stage st at: A [st*32K, st*32K+16K), B [st*32K+16K, st*32K+32K)

    // --- per-lane LDSM address components ---
    uint32_t aB[4], aX[4];
    const int cselA = mat >> 1;            // used when !AKM
    #pragma unroll
    for (int mi = 0; mi < 4; mi++) {
        if (!AKM) {
            const int row = wm + mi * 16 + ((mat & 1) << 3) + rin;
            aB[mi] = row * 128; aX[mi] = row & 7;
        } else {
            const int krb = ((mat >> 1) << 3) + rin;
            const int cm = (wm + mi * 16 + ((mat & 1) << 3)) >> 3;
            aB[mi] = krb * 256 + ((cm ^ (krb & 7)) << 4); aX[mi] = 0;
        }
    }
    uint32_t bB[4], bX[4];
    const int cselB = mat & 1;             // used when !BKN
    #pragma unroll
    for (int ni = 0; ni < 4; ni++) {
        if (!BKN) {
            const int row = wn + ni * 16 + ((mat >> 1) << 3) + rin;
            bB[ni] = row * 128; bX[ni] = row & 7;
        } else {
            const int krb = ((mat & 1) << 3) + rin;
            const int cn = (wn + ni * 16 + ((mat >> 1) << 3)) >> 3;
            bB[ni] = krb * 256 + ((cn ^ (krb & 7)) << 4); bX[ni] = 0;
        }
    }

    const int nk = K >> 6;

    auto issue = [&](int t) {
        const int kb = t << 6;
        const int st = t % 3;
        const uint32_t sa = s_base + st * 32768;
        const uint32_t sb = s_base + st * 32768 + 16384;
        #pragma unroll
        for (int i = 0; i < 8; i++) {
            const int idx = i * 128 + tid;   // 1024 16B-chunks for A
            if (!AKM) {
                const int row = idx >> 3, c = idx & 7;
                cpasync16(sa + row * 128 + ((c ^ (row & 7)) << 4),
                          Ab + (size_t)(m0 + row) * lda + kb + c * 8);
            } else {
                const int kr = idx >> 4, cm = idx & 15;
                cpasync16(sa + kr * 256 + ((cm ^ (kr & 7)) << 4),
                          Ab + (size_t)(kb + kr) * lda + m0 + cm * 8);
            }
        }
        #pragma unroll
        for (int i = 0; i < 8; i++) {
            const int idx = i * 128 + tid;   // 1024 16B-chunks for B
            if (!BKN) {
                const int row = idx >> 3, c = idx & 7;
                cpasync16(sb + row * 128 + ((c ^ (row & 7)) << 4),
                          Bb + (size_t)(n0 + row) * ldb + kb + c * 8);
            } else {
                const int kr = idx >> 4, cn = idx & 15;
                cpasync16(sb + kr * 256 + ((cn ^ (kr & 7)) << 4),
                          Bb + (size_t)(kb + kr) * ldb + n0 + cn * 8);
            }
        }
        cp_commit();
    };

    float acc[4][8][4] = {};
    uint32_t af[2][4][4];
    uint32_t bfr[2][8][2];

    issue(0);
    issue(1);

    for (int t = 0; t < nk; t++) {
        cp_wait<1>();
        __syncthreads();

        const int st = t % 3;
        const uint32_t sa = s_base + st * 32768;
        const uint32_t sb = s_base + st * 32768 + 16384;

        auto ldA = [&](int kk, int f) {
            #pragma unroll
            for (int mi = 0; mi < 4; mi++) {
                const uint32_t addr = AKM
                    ? sa + aB[mi] + kk * 4096
                    : sa + aB[mi] + ((((kk << 1) | cselA) ^ aX[mi]) << 4);
                if (!AKM) ldsm4 (af[f][mi][0], af[f][mi][1], af[f][mi][2], af[f][mi][3], addr);
                else      ldsm4t(af[f][mi][0], af[f][mi][1], af[f][mi][2], af[f][mi][3], addr);
            }
        };
        auto ldB = [&](int kk, int f) {
            #pragma unroll
            for (int ni = 0; ni < 4; ni++) {
                const uint32_t addr = BKN
                    ? sb + bB[ni] + kk * 4096
                    : sb + bB[ni] + ((((kk << 1) | cselB) ^ bX[ni]) << 4);
                uint32_t b0, b1, b2, b3;
                if (!BKN) ldsm4 (b0, b1, b2, b3, addr);
                else      ldsm4t(b0, b1, b2, b3, addr);
                bfr[f][ni * 2][0] = b0;     bfr[f][ni * 2][1] = b1;
                bfr[f][ni * 2 + 1][0] = b2; bfr[f][ni * 2 + 1][1] = b3;
            }
        };

        // first fragment loads launch immediately after the sync; the next
        // stage's cp.asyncs then overlap the LDSM latency.
        ldA(0, 0); ldB(0, 0);
        if (t + 2 < nk) issue(t + 2); else cp_commit();

        #pragma unroll
        for (int kk = 0; kk < 4; kk++) {
            const int cur = kk & 1;
            if (kk < 3) { ldA(kk + 1, cur ^ 1); ldB(kk + 1, cur ^ 1); }
            #pragma unroll
            for (int mi = 0; mi < 4; mi++)
                #pragma unroll
                for (int nj = 0; nj < 8; nj++)
                    mma_bf16(acc[mi][nj], af[cur][mi], bfr[cur][nj]);
        }
    }

    // ---------------- epilogue ----------------
    const float* Rb = RES ? R + (size_t)bz * sC : nullptr;
    #pragma unroll
    for (int mi = 0; mi < 4; mi++) {
        const int r0 = m0 + wm + mi * 16 + g;
        const int r1 = r0 + 8;
        const float bv0 = BIAS ? bias[r0] : 0.f;
        const float bv1 = BIAS ? bias[r1] : 0.f;
        #pragma unroll
        for (int nj = 0; nj < 8; nj++) {
            const int col = n0 + wn + nj * 8 + tq * 2;
            float v00 = acc[mi][nj][0] * alpha + bv0;
            float v01 = acc[mi][nj][1] * alpha + bv0;
            float v10 = acc[mi][nj][2] * alpha + bv1;
            float v11 = acc[mi][nj][3] * alpha + bv1;
            if (RES) {
                float2 x0 = *(const float2*)&Rb[(size_t)r0 * N + col];
                float2 x1 = *(const float2*)&Rb[(size_t)r1 * N + col];
                v00 += x0.x; v01 += x0.y; v10 += x1.x; v11 += x1.y;
            }
            if (OUTF) {
                float* Cb = (float*)C + (size_t)bz * sC;
                *(float2*)&Cb[(size_t)r0 * N + col] = make_float2(v00, v01);
                *(float2*)&Cb[(size_t)r1 * N + col] = make_float2(v10, v11);
            } else {
                bf16* Cb = (bf16*)C + (size_t)bz * sC;
                *(__nv_bfloat162*)&Cb[(size_t)r0 * N + col] = __floats2bfloat162_rn(v00, v01);
                *(__nv_bfloat162*)&Cb[(size_t)r1 * N + col] = __floats2bfloat162_rn(v10, v11);
            }
        }
    }
}

// ---------------------------------------------------------------------------
// Weight conversion: wq/wk/wv -> g_wqkv (concat), wp -> g_wp, biases -> g_bqkv
// ---------------------------------------------------------------------------
__global__ void __launch_bounds__(256) wcvt_kernel(
    const float* __restrict__ wq, const float* __restrict__ wk,
    const float* __restrict__ wv, const float* __restrict__ wp,
    const float* __restrict__ bq, const float* __restrict__ bk,
    const float* __restrict__ bv)
{
    const int i = (blockIdx.x * 256 + threadIdx.x) * 4;
    if (i < NC * NC) {
        const float* src[4] = {wq, wk, wv, wp};
        bf16* dst[4] = {g_wqkv, g_wqkv + NC * NC, g_wqkv + 2 * NC * NC, g_wp};
        #pragma unroll
        for (int j = 0; j < 4; j++) {
            float4 v = *(const float4*)(src[j] + i);
            *(__nv_bfloat162*)(dst[j] + i)     = __floats2bfloat162_rn(v.x, v.y);
            *(__nv_bfloat162*)(dst[j] + i + 2) = __floats2bfloat162_rn(v.z, v.w);
        }
    }
    const int t = blockIdx.x * 256 + threadIdx.x;
    if (t < NC) {
        g_bqkv[t]          = bq[t];
        g_bqkv[t + NC]     = bk[t];
        g_bqkv[t + 2 * NC] = bv[t];
    }
}

// ---------------------------------------------------------------------------
// GroupNorm: one block per (batch, group). Writes bf16 xn (c, hw).
// ---------------------------------------------------------------------------
__global__ void __launch_bounds__(256) gn_kernel(const float* __restrict__ x,
                                                 const float* __restrict__ gamma,
                                                 const float* __restrict__ beta) {
    const int bg = blockIdx.x;
    const int b = bg >> 5, g = bg & 31;
    const size_t base = ((size_t)b * NC + (size_t)g * 16) * NHW;
    const float* xp = x + base;
    bf16* op = g_xn + base;
    const int N = 16 * NHW;

    float s = 0.f, ss = 0.f;
    for (int i = threadIdx.x * 4; i < N; i += 256 * 4) {
        float4 v = *(const float4*)(xp + i);
        s  += v.x + v.y + v.z + v.w;
        ss += v.x*v.x + v.y*v.y + v.z*v.z + v.w*v.w;
    }
    __shared__ float rs[8], rq[8];
    #pragma unroll
    for (int o = 16; o > 0; o >>= 1) {
        s  += __shfl_xor_sync(0xffffffffu, s,  o);
        ss += __shfl_xor_sync(0xffffffffu, ss, o);
    }
    if ((threadIdx.x & 31) == 0) { rs[threadIdx.x >> 5] = s; rq[threadIdx.x >> 5] = ss; }
    __syncthreads();
    s = 0.f; ss = 0.f;
    #pragma unroll
    for (int w = 0; w < 8; w++) { s += rs[w]; ss += rq[w]; }

    const float mean = s / (float)N;
    const float var  = ss / (float)N - mean * mean;
    const float rstd = rsqrtf(var + 1e-6f);

    for (int i = threadIdx.x * 4; i < N; i += 256 * 4) {
        const int c = g * 16 + (i >> 10);
        const float gm = gamma[c] * rstd;
        const float bt = beta[c] - mean * gm;
        float4 v = *(const float4*)(xp + i);
        *(__nv_bfloat162*)(op + i)     = __floats2bfloat162_rn(v.x * gm + bt, v.y * gm + bt);
        *(__nv_bfloat162*)(op + i + 2) = __floats2bfloat162_rn(v.z * gm + bt, v.w * gm + bt);
    }
}

// ---------------------------------------------------------------------------
// Softmax rows of g_e (f32, 1024 wide) -> g_ah (bf16). One block per row.
// ---------------------------------------------------------------------------
__global__ void __launch_bounds__(256) softmax_kernel() {
    const size_t row = blockIdx.x;
    const float* p = g_e + row * NHW;
    bf16* q = g_ah + row * NHW;
    const int tid = threadIdx.x;

    float4 v = ((const float4*)p)[tid];
    float mx = fmaxf(fmaxf(v.x, v.y), fmaxf(v.z, v.w));
    __shared__ float sm[8], ssum[8];
    #pragma unroll
    for (int o = 16; o > 0; o >>= 1) mx = fmaxf(mx, __shfl_xor_sync(0xffffffffu, mx, o));
    if ((tid & 31) == 0) sm[tid >> 5] = mx;
    __syncthreads();
    mx = sm[0];
    #pragma unroll
    for (int w = 1; w < 8; w++) mx = fmaxf(mx, sm[w]);

    v.x = __expf(v.x - mx); v.y = __expf(v.y - mx);
    v.z = __expf(v.z - mx); v.w = __expf(v.w - mx);
    float s = v.x + v.y + v.z + v.w;
    #pragma unroll
    for (int o = 16; o > 0; o >>= 1) s += __shfl_xor_sync(0xffffffffu, s, o);
    if ((tid & 31) == 0) ssum[tid >> 5] = s;
    __syncthreads();
    s = 0.f;
    #pragma unroll
    for (int w = 0; w < 8; w++) s += ssum[w];

    const float inv = 1.0f / s;
    *(__nv_bfloat162*)(q + tid * 4)     = __floats2bfloat162_rn(v.x * inv, v.y * inv);
    *(__nv_bfloat162*)(q + tid * 4 + 2) = __floats2bfloat162_rn(v.z * inv, v.w * inv);
}

// ---------------------------------------------------------------------------
// Launch
// ---------------------------------------------------------------------------
#define SMEM_DYN 98304

extern "C" void kernel_launch(void* const* d_in, const int* in_sizes, int n_in,
                              void* d_out, int out_size) {
    const float* x     = (const float*)d_in[0];
    const float* gamma = (const float*)d_in[1];
    const float* beta  = (const float*)d_in[2];
    const float* wq = (const float*)d_in[3]; const float* bq = (const float*)d_in[4];
    const float* wk = (const float*)d_in[5]; const float* bk = (const float*)d_in[6];
    const float* wv = (const float*)d_in[7]; const float* bv = (const float*)d_in[8];
    const float* wp = (const float*)d_in[9]; const float* bp = (const float*)d_in[10];

    bf16 *p_xn, *p_qkv, *p_o, *p_ah, *p_wqkv, *p_wp;
    float *p_e, *p_bqkv;
    cudaGetSymbolAddress((void**)&p_xn,   g_xn);
    cudaGetSymbolAddress((void**)&p_qkv,  g_qkv);
    cudaGetSymbolAddress((void**)&p_o,    g_o);
    cudaGetSymbolAddress((void**)&p_ah,   g_ah);
    cudaGetSymbolAddress((void**)&p_e,    g_e);
    cudaGetSymbolAddress((void**)&p_wqkv, g_wqkv);
    cudaGetSymbolAddress((void**)&p_wp,   g_wp);
    cudaGetSymbolAddress((void**)&p_bqkv, g_bqkv);

    cudaFuncSetAttribute(mm_bf16<false,true,false,true,false>,
                         cudaFuncAttributeMaxDynamicSharedMemorySize, SMEM_DYN);
    cudaFuncSetAttribute(mm_bf16<true,true,true,false,false>,
                         cudaFuncAttributeMaxDynamicSharedMemorySize, SMEM_DYN);
    cudaFuncSetAttribute(mm_bf16<false,false,false,false,false>,
                         cudaFuncAttributeMaxDynamicSharedMemorySize, SMEM_DYN);
    cudaFuncSetAttribute(mm_bf16<false,true,true,true,true>,
                         cudaFuncAttributeMaxDynamicSharedMemorySize, SMEM_DYN);

    const size_t sX   = (size_t)NC * NHW;        // per-batch (c, hw)
    const size_t sQKV = (size_t)3 * NC * NHW;    // per-batch (1536, hw)
    const size_t sE   = (size_t)NHW * NHW;

    const bf16* p_q = p_qkv;                 // rows 0..511    of (1536, hw)
    const bf16* p_k = p_qkv + NC * NHW;      // rows 512..1023
    const bf16* p_v = p_qkv + 2 * NC * NHW;  // rows 1024..1535

    wcvt_kernel<<<NC * NC / (256 * 4), 256>>>(wq, wk, wv, wp, bq, bk, bv);
    gn_kernel<<<NB * 32, 256>>>(x, gamma, beta);

    // fused qkv: (1536 x 1024) = Wqkv(m,k) . xn(k,n) + bias -> g_qkv, bf16
    mm_bf16<false,true,false,true,false><<<dim3(NHW/128, 3*NC/128, NB), 128, SMEM_DYN>>>(
        p_wqkv, p_xn, p_bqkv, nullptr, p_qkv, NHW, NC, NC, NHW, 0, sX, sQKV, 1.f);

    // energy(1024x1024) = alpha * q^T k  (A (k,m), B (k,n)), f32 out
    mm_bf16<true,true,true,false,false><<<dim3(NHW/128, NHW/128, NB), 128, SMEM_DYN>>>(
        p_q, p_k, nullptr, nullptr, p_e, NHW, NC, NHW, NHW, sQKV, sQKV, sE,
        0.04419417382415922f);

    softmax_kernel<<<NB * NHW, 256>>>();

    // O(512x1024) = V(m,k) . attn(n,k), bf16 out
    mm_bf16<false,false,false,false,false><<<dim3(NHW/128, NC/128, NB), 128, SMEM_DYN>>>(
        p_v, p_ah, nullptr, nullptr, p_o, NHW, NHW, NHW, NHW, sQKV, sE, sX, 1.f);

    // proj + bias + residual -> f32 d_out
    mm_bf16<false,true,true,true,true><<<dim3(NHW/128, NC/128, NB), 128, SMEM_DYN>>>(
        p_wp, p_o, bp, x, d_out, NHW, NC, NC, NHW, 0, sX, sX, 1.f);
}